// round 14
// baseline (speedup 1.0000x reference)
#include <cuda.h>
#include <cuda_runtime.h>
#include <cuda_bf16.h>
#include <math.h>
#include <stdint.h>

// ---------------- problem constants ----------------
#define BB   16
#define CIN  512
#define COUT 512
#define HW   4096
#define MCB  192
#define EPS_BN 1e-5f
#define BK   32

typedef __nv_bfloat16 bf16;

#define SWZ(o) ((o) ^ (((o) >> 3) & 0x30))

// ---------------- scratch (device globals) ----------------
__device__ bf16  g_xT_h [(size_t)BB * HW * CIN];
__device__ bf16  g_xT_l [(size_t)BB * HW * CIN];
__device__ bf16  g_b1_h [(size_t)BB * HW * COUT];
__device__ bf16  g_b1_l [(size_t)BB * HW * COUT];
__device__ bf16  g_b2_h [(size_t)BB * HW * CIN];
__device__ bf16  g_b2_l [(size_t)BB * HW * CIN];
__device__ float g_buf1 [(size_t)BB * HW * COUT];
__device__ float g_att  [(size_t)BB * HW * MCB];
__device__ bf16  g_att_h[(size_t)BB * HW * MCB];
__device__ bf16  g_att_l[(size_t)BB * HW * MCB];
__device__ bf16  g_ct_h [MCB * COUT];
__device__ bf16  g_ct_l [MCB * COUT];
__device__ bf16  g_cs_h [(size_t)BB * COUT * MCB];
__device__ bf16  g_cs_l [(size_t)BB * COUT * MCB];
__device__ bf16  g_w1_h [COUT * CIN];
__device__ bf16  g_w1_l [COUT * CIN];
__device__ bf16  g_w2_h [CIN * COUT];
__device__ bf16  g_w2_l [CIN * COUT];
__device__ bf16  g_w3_h [CIN * CIN];
__device__ bf16  g_w3_l [CIN * CIN];
__device__ float g_colsum[BB * MCB];
__device__ float g_sumA [CIN];
__device__ float g_sum2A[CIN];
__device__ float g_sumB [CIN];
__device__ float g_sum2B[CIN];

// ---------------- device helpers ----------------
__device__ __forceinline__ uint32_t smem_u32(const void* p) {
    uint32_t a;
    asm("{ .reg .u64 t; cvta.to.shared.u64 t, %1; cvt.u32.u64 %0, t; }" : "=r"(a) : "l"(p));
    return a;
}
__device__ __forceinline__ void ldmatrix_x4(uint32_t& r0, uint32_t& r1, uint32_t& r2, uint32_t& r3, uint32_t addr) {
    asm volatile("ldmatrix.sync.aligned.m8n8.x4.shared.b16 {%0,%1,%2,%3}, [%4];"
                 : "=r"(r0), "=r"(r1), "=r"(r2), "=r"(r3) : "r"(addr));
}
__device__ __forceinline__ void ldmatrix_x2(uint32_t& r0, uint32_t& r1, uint32_t addr) {
    asm volatile("ldmatrix.sync.aligned.m8n8.x2.shared.b16 {%0,%1}, [%2];"
                 : "=r"(r0), "=r"(r1) : "r"(addr));
}
__device__ __forceinline__ void mma_bf16(float* c, uint32_t a0, uint32_t a1, uint32_t a2, uint32_t a3,
                                         uint32_t b0, uint32_t b1) {
    asm("mma.sync.aligned.m16n8k16.row.col.f32.bf16.bf16.f32 "
        "{%0,%1,%2,%3}, {%4,%5,%6,%7}, {%8,%9}, {%0,%1,%2,%3};"
        : "+f"(c[0]), "+f"(c[1]), "+f"(c[2]), "+f"(c[3])
        : "r"(a0), "r"(a1), "r"(a2), "r"(a3), "r"(b0), "r"(b1));
}
__device__ __forceinline__ uint32_t pack_bf2(float x, float y) {
    __nv_bfloat162 h = __floats2bfloat162_rn(x, y);
    return *(uint32_t*)&h;
}
__device__ __forceinline__ void split1(float v, bf16& h, bf16& l) {
    h = __float2bfloat16_rn(v);
    l = __float2bfloat16_rn(v - __bfloat162float(h));
}

#define MBARRIER_INIT(addr, cnt) \
    asm volatile("mbarrier.init.shared.b64 [%0], %1;" :: "r"((uint32_t)(addr)), "r"((uint32_t)(cnt)) : "memory")
#define MBARRIER_EXPECT_TX(addr, tx) \
    asm volatile("mbarrier.arrive.expect_tx.shared.b64 _, [%0], %1;" :: "r"((uint32_t)(addr)), "r"((uint32_t)(tx)) : "memory")
#define MBARRIER_ARRIVE(addr) \
    asm volatile("mbarrier.arrive.shared.b64 _, [%0];" :: "r"((uint32_t)(addr)) : "memory")
#define MBARRIER_WAIT_PARITY(addr, par) do { \
    uint32_t _m = (uint32_t)(addr); uint32_t _p = (uint32_t)(par); uint32_t _d; \
    asm volatile("{\n\t.reg .pred p;\n\tmbarrier.try_wait.parity.acquire.cta.shared::cta.b64 p, [%1], %2;\n\tselp.b32 %0, 1, 0, p;\n\t}" \
        : "=r"(_d) : "r"(_m), "r"(_p) : "memory"); \
    if (!_d) { \
        asm volatile("{\n\t.reg .pred P1;\n\tWL_%=:\n\tmbarrier.try_wait.parity.acquire.cta.shared::cta.b64 P1, [%0], %1, 0x989680;\n\t@P1 bra.uni WD_%=;\n\tbra.uni WL_%=;\n\tWD_%=:\n\t}" \
            :: "r"(_m), "r"(_p) : "memory"); \
    } } while (0)
#define TMA2D(dst, map, cx, cy, bar) \
    asm volatile("cp.async.bulk.tensor.2d.shared::cta.global.tile.mbarrier::complete_tx::bytes " \
                 "[%0], [%1, {%2, %3}], [%4];" \
        :: "r"((uint32_t)(dst)), "l"(map), "r"((int)(cx)), "r"((int)(cy)), "r"((uint32_t)(bar)) : "memory")

// ---------------- split bf16x3 GEMM, 3-stage TMA pipeline ----------------
// Lane0-only barrier waits + __syncwarp broadcast. Per-warp empty mbars.
template<int NT, bool BIAS, bool SPLIT_OUT, bool BNSTAT>
__global__ __launch_bounds__(256, 2)
void gemm_tma(const __grid_constant__ CUtensorMap mAh,
              const __grid_constant__ CUtensorMap mAl,
              const __grid_constant__ CUtensorMap mBh,
              const __grid_constant__ CUtensorMap mBl,
              const float* __restrict__ bias,
              float* __restrict__ Cf, bf16* __restrict__ Chp, bf16* __restrict__ Clp,
              float* __restrict__ gsum, float* __restrict__ gsum2,
              int Kd, int Ntot, int bZmul, size_t cS)
{
    constexpr int WN = NT / 4;
    constexpr int NF = WN / 8;
    constexpr int OFF_AL = 8192;
    constexpr int OFF_BH = 16384;
    constexpr int OFF_BL = 16384 + NT * 64;
    constexpr int STAGE  = 16384 + 2 * NT * 64;

    extern __shared__ __align__(1024) char dsm[];
    __shared__ __align__(8) uint64_t mbar_full[3];
    __shared__ __align__(8) uint64_t mbar_empty[3];
    __shared__ float bn_s[NT];
    __shared__ float bn_s2[NT];

    const uint32_t sbase = smem_u32(dsm);
    const int tid = threadIdx.x;
    const int lane = tid & 31;
    const int wid = tid >> 5;
    const int wm = wid & 1;
    const int wn = wid >> 1;
    const int m0 = blockIdx.y * 128;
    const int n0 = blockIdx.x * NT;
    const int z  = blockIdx.z;

    const int NC = Kd / BK;
    const int cyA = z * HW + m0;
    const int cyB = z * bZmul + n0;

    if (tid == 0) {
#pragma unroll
        for (int s = 0; s < 3; ++s) {
            MBARRIER_INIT(smem_u32(&mbar_full[s]), 1);
            MBARRIER_INIT(smem_u32(&mbar_empty[s]), 8);
        }
    }
    if (BNSTAT) {
        for (int t = tid; t < NT; t += 256) { bn_s[t] = 0.f; bn_s2[t] = 0.f; }
    }
    __syncthreads();

    auto issue = [&](int i) {
        const int s = i % 3;
        const uint32_t bar = smem_u32(&mbar_full[s]);
        const uint32_t st = sbase + s * STAGE;
        MBARRIER_EXPECT_TX(bar, (uint32_t)STAGE);
        const int cx = i * BK;
        TMA2D(st,          &mAh, cx, cyA, bar);
        TMA2D(st + OFF_AL, &mAl, cx, cyA, bar);
        TMA2D(st + OFF_BH, &mBh, cx, cyB, bar);
        TMA2D(st + OFF_BL, &mBl, cx, cyB, bar);
    };
    if (tid == 0) { issue(0); issue(1); issue(2); }

    float acc[4][NF][4];
#pragma unroll
    for (int mi = 0; mi < 4; ++mi)
#pragma unroll
        for (int ni = 0; ni < NF; ++ni)
#pragma unroll
            for (int j = 0; j < 4; ++j) acc[mi][ni][j] = 0.f;

    const int arow = wm * 64;
    const int brow = wn * WN;
    const int l7 = lane & 7;
    const int aq = lane >> 3;
    const int arsel = (aq & 1) * 8;
    const int acsel = (aq >> 1) * 16;
    const int b4r = ((lane >> 4) & 1) * 8;
    const int b4c = ((lane >> 3) & 1) * 16;
    const int b2c = ((lane >> 3) & 1) * 16;

    for (int i = 0; i < NC; ++i) {
        const int s = i % 3;
        const int par = (i / 3) & 1;
        // lane0-only wait, broadcast via syncwarp (acquire on lane0 +
        // syncwarp ordering covers the warp's subsequent ldsm)
        if (lane == 0) MBARRIER_WAIT_PARITY(smem_u32(&mbar_full[s]), par);
        __syncwarp();

        const uint32_t st = sbase + s * STAGE;
        const uint32_t sAh = st;
        const uint32_t sAl = st + OFF_AL;
        const uint32_t sBh = st + OFF_BH;
        const uint32_t sBl = st + OFF_BL;

#pragma unroll
        for (int k16 = 0; k16 < 2; ++k16) {
            const int kb = k16 * 32;
            uint32_t bh[NF][2], bl[NF][2];
#pragma unroll
            for (int p = 0; p < NF / 2; ++p) {
                uint32_t bo = SWZ((uint32_t)((brow + p * 16 + b4r + l7) * 64 + kb + b4c));
                ldmatrix_x4(bh[2*p][0], bh[2*p][1], bh[2*p+1][0], bh[2*p+1][1], sBh + bo);
                ldmatrix_x4(bl[2*p][0], bl[2*p][1], bl[2*p+1][0], bl[2*p+1][1], sBl + bo);
            }
            if (NF & 1) {
                const int ni = NF - 1;
                uint32_t bo = SWZ((uint32_t)((brow + ni * 8 + l7) * 64 + kb + b2c));
                ldmatrix_x2(bh[ni][0], bh[ni][1], sBh + bo);
                ldmatrix_x2(bl[ni][0], bl[ni][1], sBl + bo);
            }
#pragma unroll
            for (int mi = 0; mi < 4; ++mi) {
                uint32_t ao = SWZ((uint32_t)((arow + mi * 16 + arsel + l7) * 64 + kb + acsel));
                uint32_t ah0, ah1, ah2, ah3, al0, al1, al2, al3;
                ldmatrix_x4(ah0, ah1, ah2, ah3, sAh + ao);
                ldmatrix_x4(al0, al1, al2, al3, sAl + ao);
#pragma unroll
                for (int ni = 0; ni < NF; ++ni)
                    mma_bf16(acc[mi][ni], ah0, ah1, ah2, ah3, bh[ni][0], bh[ni][1]);
#pragma unroll
                for (int ni = 0; ni < NF; ++ni)
                    mma_bf16(acc[mi][ni], ah0, ah1, ah2, ah3, bl[ni][0], bl[ni][1]);
#pragma unroll
                for (int ni = 0; ni < NF; ++ni)
                    mma_bf16(acc[mi][ni], al0, al1, al2, al3, bh[ni][0], bh[ni][1]);
            }
        }

        if (lane == 0) MBARRIER_ARRIVE(smem_u32(&mbar_empty[s]));
        if (tid == 0 && i + 3 < NC) {
            MBARRIER_WAIT_PARITY(smem_u32(&mbar_empty[s]), par);
            issue(i + 3);
        }
    }

    // ---- epilogue ----
    const int l4 = lane >> 2;
    const int lc = (lane & 3) * 2;
    float ps0[NF], ps1[NF], q0s[NF], q1s[NF];
#pragma unroll
    for (int ni = 0; ni < NF; ++ni) { ps0[ni] = ps1[ni] = q0s[ni] = q1s[ni] = 0.f; }

#pragma unroll
    for (int mi = 0; mi < 4; ++mi) {
        const int row = m0 + wm * 64 + mi * 16 + l4;
#pragma unroll
        for (int ni = 0; ni < NF; ++ni) {
            const int col = n0 + wn * WN + ni * 8 + lc;
            float b0 = BIAS ? bias[col] : 0.f;
            float b1 = BIAS ? bias[col + 1] : 0.f;
            float v00 = acc[mi][ni][0] + b0, v01 = acc[mi][ni][1] + b1;
            float v10 = acc[mi][ni][2] + b0, v11 = acc[mi][ni][3] + b1;
            if (BNSTAT) {
                ps0[ni] += v00 + v10;  q0s[ni] += v00 * v00 + v10 * v10;
                ps1[ni] += v01 + v11;  q1s[ni] += v01 * v01 + v11 * v11;
            }
            if (SPLIT_OUT) {
                bf16 h0, l0, h1, l1;
                size_t o0 = (size_t)z * cS + (size_t)row * Ntot + col;
                size_t o1 = (size_t)z * cS + (size_t)(row + 8) * Ntot + col;
                split1(v00, h0, l0); split1(v01, h1, l1);
                *(uint32_t*)(Chp + o0) = pack_bf2(__bfloat162float(h0), __bfloat162float(h1));
                *(uint32_t*)(Clp + o0) = pack_bf2(__bfloat162float(l0), __bfloat162float(l1));
                split1(v10, h0, l0); split1(v11, h1, l1);
                *(uint32_t*)(Chp + o1) = pack_bf2(__bfloat162float(h0), __bfloat162float(h1));
                *(uint32_t*)(Clp + o1) = pack_bf2(__bfloat162float(l0), __bfloat162float(l1));
            } else {
                float* C = Cf + (size_t)z * cS;
                float2 w0 = { v00, v01 };
                float2 w1 = { v10, v11 };
                *(float2*)(C + (size_t)row * Ntot + col) = w0;
                *(float2*)(C + (size_t)(row + 8) * Ntot + col) = w1;
            }
        }
    }

    if (BNSTAT) {
        __syncthreads();   // bn_s zero-init (pre-mainloop) is visible; order before atomics
#pragma unroll
        for (int ni = 0; ni < NF; ++ni) {
            float a = ps0[ni], b = ps1[ni], c = q0s[ni], d = q1s[ni];
#pragma unroll
            for (int o = 4; o <= 16; o <<= 1) {
                a += __shfl_xor_sync(0xffffffffu, a, o);
                b += __shfl_xor_sync(0xffffffffu, b, o);
                c += __shfl_xor_sync(0xffffffffu, c, o);
                d += __shfl_xor_sync(0xffffffffu, d, o);
            }
            if (lane < 4) {
                int cl = wn * WN + ni * 8 + lc;
                atomicAdd(&bn_s[cl], a);  atomicAdd(&bn_s[cl + 1], b);
                atomicAdd(&bn_s2[cl], c); atomicAdd(&bn_s2[cl + 1], d);
            }
        }
        __syncthreads();
        for (int t = tid; t < NT; t += 256) {
            atomicAdd(&gsum[n0 + t], bn_s[t]);
            atomicAdd(&gsum2[n0 + t], bn_s2[t]);
        }
    }
}

// ---------------- prep kernels ----------------
__global__ void zero_all_kernel(float* cs, float* sA, float* s2A, float* sB, float* s2B)
{
    int i = blockIdx.x * 1024 + threadIdx.x;
    if (i < BB * MCB) cs[i] = 0.f;
    if (i < CIN) { sA[i] = 0.f; s2A[i] = 0.f; sB[i] = 0.f; s2B[i] = 0.f; }
}

__global__ void prep_split_kernel(const float* __restrict__ w1, const float* __restrict__ w2,
                                  const float* __restrict__ w3, const float* __restrict__ cen,
                                  bf16* __restrict__ w1h, bf16* __restrict__ w1l,
                                  bf16* __restrict__ w2h, bf16* __restrict__ w2l,
                                  bf16* __restrict__ w3h, bf16* __restrict__ w3l,
                                  bf16* __restrict__ cth, bf16* __restrict__ ctl)
{
    const int W = COUT * CIN;
    const int CT = COUT * MCB;
    int i = blockIdx.x * 256 + threadIdx.x;
    bf16 hh, ll;
    if (i < W) {
        split1(w1[i], hh, ll); w1h[i] = hh; w1l[i] = ll;
    } else if (i < 2 * W) {
        int j = i - W;
        split1(w2[j], hh, ll); w2h[j] = hh; w2l[j] = ll;
    } else if (i < 3 * W) {
        int j = i - 2 * W;
        split1(w3[j], hh, ll); w3h[j] = hh; w3l[j] = ll;
    } else if (i < 3 * W + CT) {
        int j = i - 3 * W;
        int c = j / MCB, k = j % MCB;
        split1(cen[j], hh, ll);
        cth[k * COUT + c] = hh; ctl[k * COUT + c] = ll;
    }
}

__global__ void transpose_in_split(const float* __restrict__ in, bf16* __restrict__ oh, bf16* __restrict__ ol)
{
    __shared__ float t[32][33];
    const int b = blockIdx.z;
    const int n0 = blockIdx.x * 32, c0 = blockIdx.y * 32;
    const float* ip = in + (size_t)b * CIN * HW;
#pragma unroll
    for (int i = 0; i < 32; i += 8)
        t[threadIdx.y + i][threadIdx.x] = ip[(size_t)(c0 + threadIdx.y + i) * HW + n0 + threadIdx.x];
    __syncthreads();
#pragma unroll
    for (int i = 0; i < 32; i += 8) {
        float v = t[threadIdx.x][threadIdx.y + i];
        bf16 hh, ll;
        split1(v, hh, ll);
        size_t o = (size_t)b * HW * CIN + (size_t)(n0 + threadIdx.y + i) * CIN + c0 + threadIdx.x;
        oh[o] = hh; ol[o] = ll;
    }
}

__global__ void scale_centers_split(const float* __restrict__ centers, const float* __restrict__ colsum,
                                    bf16* __restrict__ oh, bf16* __restrict__ ol)
{
    int i = blockIdx.x * 256 + threadIdx.x;
    int b = blockIdx.y;
    if (i < COUT * MCB) {
        int k = i % MCB;
        float r = 1.f / (1e-6f + colsum[b * MCB + k]);
        float v = centers[i] * r;
        bf16 hh, ll;
        split1(v, hh, ll);
        size_t o = (size_t)b * COUT * MCB + i;
        oh[o] = hh; ol[o] = ll;
    }
}

// ---------------- softmax: single pass, split planes + colsum ----------------
__global__ void softmax_colsum_split(const float* __restrict__ att, float* __restrict__ colsum,
                                     bf16* __restrict__ oh, bf16* __restrict__ ol)
{
    const int warp = threadIdx.x >> 5;
    const int lane = threadIdx.x & 31;
    const int b = blockIdx.y;
    const int rowBase = blockIdx.x * 256 + warp * 32;
    float cacc[6] = {0.f, 0.f, 0.f, 0.f, 0.f, 0.f};

    for (int r = 0; r < 32; ++r) {
        const int n = rowBase + r;
        const size_t base = ((size_t)b * HW + n) * MCB;
        const float* p = att + base;
        float v[6];
        float mx = -1e30f;
#pragma unroll
        for (int j = 0; j < 6; ++j) { v[j] = p[j * 32 + lane]; mx = fmaxf(mx, v[j]); }
#pragma unroll
        for (int o = 16; o > 0; o >>= 1) mx = fmaxf(mx, __shfl_xor_sync(0xffffffffu, mx, o));
        float s = 0.f;
#pragma unroll
        for (int j = 0; j < 6; ++j) { v[j] = expf(v[j] - mx); s += v[j]; }
#pragma unroll
        for (int o = 16; o > 0; o >>= 1) s += __shfl_xor_sync(0xffffffffu, s, o);
        const float inv = 1.f / s;
#pragma unroll
        for (int j = 0; j < 6; ++j) {
            float ov = v[j] * inv;
            cacc[j] += ov;
            bf16 hh, ll;
            split1(ov, hh, ll);
            oh[base + j * 32 + lane] = hh;
            ol[base + j * 32 + lane] = ll;
        }
    }
#pragma unroll
    for (int j = 0; j < 6; ++j)
        atomicAdd(&colsum[b * MCB + j * 32 + lane], cacc[j]);
}

// ---------------- BN apply (inline finalize) ----------------
__global__ void bn_apply_res_split(const float* __restrict__ t,
                                   const bf16* __restrict__ xh, const bf16* __restrict__ xl,
                                   const float* __restrict__ gsum, const float* __restrict__ gsum2,
                                   const float* __restrict__ gamma, const float* __restrict__ beta,
                                   bf16* __restrict__ oh, bf16* __restrict__ ol)
{
    size_t i = (size_t)blockIdx.x * blockDim.x + threadIdx.x;
    const int c4 = (int)(i & 127);
    const float N = (float)((size_t)BB * HW);
    const float4 sm = ((const float4*)gsum)[c4];
    const float4 s2 = ((const float4*)gsum2)[c4];
    const float4 gm = ((const float4*)gamma)[c4];
    const float4 bt = ((const float4*)beta)[c4];
    float4 sc, sh;
    {
        float m, vr;
        m = sm.x / N; vr = s2.x / N - m * m; sc.x = gm.x * rsqrtf(vr + EPS_BN); sh.x = bt.x - m * sc.x;
        m = sm.y / N; vr = s2.y / N - m * m; sc.y = gm.y * rsqrtf(vr + EPS_BN); sh.y = bt.y - m * sc.y;
        m = sm.z / N; vr = s2.z / N - m * m; sc.z = gm.z * rsqrtf(vr + EPS_BN); sh.z = bt.z - m * sc.z;
        m = sm.w / N; vr = s2.w / N - m * m; sc.w = gm.w * rsqrtf(vr + EPS_BN); sh.w = bt.w - m * sc.w;
    }
    float4 v = ((const float4*)t)[i];
    uint2 xhu = *(const uint2*)(xh + i * 4);
    uint2 xlu = *(const uint2*)(xl + i * 4);
    __nv_bfloat162 xh0 = *(__nv_bfloat162*)&xhu.x;
    __nv_bfloat162 xh1 = *(__nv_bfloat162*)&xhu.y;
    __nv_bfloat162 xl0 = *(__nv_bfloat162*)&xlu.x;
    __nv_bfloat162 xl1 = *(__nv_bfloat162*)&xlu.y;
    v.x = fmaxf(fmaf(sc.x, v.x, sh.x), 0.f) + __bfloat162float(xh0.x) + __bfloat162float(xl0.x);
    v.y = fmaxf(fmaf(sc.y, v.y, sh.y), 0.f) + __bfloat162float(xh0.y) + __bfloat162float(xl0.y);
    v.z = fmaxf(fmaf(sc.z, v.z, sh.z), 0.f) + __bfloat162float(xh1.x) + __bfloat162float(xl1.x);
    v.w = fmaxf(fmaf(sc.w, v.w, sh.w), 0.f) + __bfloat162float(xh1.y) + __bfloat162float(xl1.y);
    bf16 hx, lx, hy, ly, hz, lz, hw, lw;
    split1(v.x, hx, lx); split1(v.y, hy, ly); split1(v.z, hz, lz); split1(v.w, hw, lw);
    uint2 ho = { pack_bf2(__bfloat162float(hx), __bfloat162float(hy)),
                 pack_bf2(__bfloat162float(hz), __bfloat162float(hw)) };
    uint2 lo = { pack_bf2(__bfloat162float(lx), __bfloat162float(ly)),
                 pack_bf2(__bfloat162float(lz), __bfloat162float(lw)) };
    *(uint2*)(oh + i * 4) = ho;
    *(uint2*)(ol + i * 4) = lo;
}

__global__ void bn_apply_transpose_kernel(const float* __restrict__ in,
                                          const float* __restrict__ gsum, const float* __restrict__ gsum2,
                                          const float* __restrict__ gamma, const float* __restrict__ beta,
                                          float* __restrict__ out)
{
    __shared__ float t[32][33];
    const int b = blockIdx.z;
    const int n0 = blockIdx.x * 32, c0 = blockIdx.y * 32;
    const float* ip = in + (size_t)b * HW * CIN;
    float* op = out + (size_t)b * CIN * HW;
    const int c = c0 + threadIdx.x;
    const float N = (float)((size_t)BB * HW);
    const float mean = gsum[c] / N;
    const float var = gsum2[c] / N - mean * mean;
    const float sc = gamma[c] * rsqrtf(var + EPS_BN);
    const float sh = beta[c] - mean * sc;
#pragma unroll
    for (int i = 0; i < 32; i += 8) {
        float v = ip[(size_t)(n0 + threadIdx.y + i) * CIN + c];
        t[threadIdx.y + i][threadIdx.x] = fmaxf(fmaf(sc, v, sh), 0.f);
    }
    __syncthreads();
#pragma unroll
    for (int i = 0; i < 32; i += 8)
        op[(size_t)(c0 + threadIdx.y + i) * HW + n0 + threadIdx.x] = t[threadIdx.x][threadIdx.y + i];
}

// ---------------- host-side tensor map helper ----------------
typedef CUresult (*EncFn)(CUtensorMap*, CUtensorMapDataType, cuuint32_t, void*,
                          const cuuint64_t*, const cuuint64_t*, const cuuint32_t*, const cuuint32_t*,
                          CUtensorMapInterleave, CUtensorMapSwizzle, CUtensorMapL2promotion,
                          CUtensorMapFloatOOBfill);

static void make_map(EncFn enc, CUtensorMap* m, void* base, uint64_t kd, uint64_t rows, uint32_t box_rows)
{
    cuuint64_t dims[2] = { kd, rows };
    cuuint64_t strides[1] = { kd * 2 };
    cuuint32_t box[2] = { 32, box_rows };
    cuuint32_t es[2] = { 1, 1 };
    enc(m, CU_TENSOR_MAP_DATA_TYPE_BFLOAT16, 2, base, dims, strides, box, es,
        CU_TENSOR_MAP_INTERLEAVE_NONE, CU_TENSOR_MAP_SWIZZLE_64B,
        CU_TENSOR_MAP_L2_PROMOTION_L2_128B, CU_TENSOR_MAP_FLOAT_OOB_FILL_NONE);
}

// ---------------- launch ----------------
extern "C" void kernel_launch(void* const* d_in, const int* in_sizes, int n_in,
                              void* d_out, int out_size)
{
    const float* x       = (const float*)d_in[0];
    const float* centers = (const float*)d_in[1];
    const float* conv1_w = (const float*)d_in[2];
    const float* conv1_b = (const float*)d_in[3];
    const float* conv2_w = (const float*)d_in[4];
    const float* bn2_g   = (const float*)d_in[5];
    const float* bn2_b   = (const float*)d_in[6];
    const float* conv3_w = (const float*)d_in[7];
    const float* conv3_b = (const float*)d_in[8];
    const float* bn3_g   = (const float*)d_in[9];
    const float* bn3_b   = (const float*)d_in[10];
    float* out = (float*)d_out;

    bf16 *xTh, *xTl, *b1h, *b1l, *b2h, *b2l, *atth, *attl, *cth, *ctl, *csh, *csl;
    bf16 *w1h, *w1l, *w2h, *w2l, *w3h, *w3l;
    float *buf1, *att, *colsum, *sumA, *sum2A, *sumB, *sum2B;
    cudaGetSymbolAddress((void**)&xTh, g_xT_h);  cudaGetSymbolAddress((void**)&xTl, g_xT_l);
    cudaGetSymbolAddress((void**)&b1h, g_b1_h);  cudaGetSymbolAddress((void**)&b1l, g_b1_l);
    cudaGetSymbolAddress((void**)&b2h, g_b2_h);  cudaGetSymbolAddress((void**)&b2l, g_b2_l);
    cudaGetSymbolAddress((void**)&atth, g_att_h); cudaGetSymbolAddress((void**)&attl, g_att_l);
    cudaGetSymbolAddress((void**)&cth, g_ct_h);  cudaGetSymbolAddress((void**)&ctl, g_ct_l);
    cudaGetSymbolAddress((void**)&csh, g_cs_h);  cudaGetSymbolAddress((void**)&csl, g_cs_l);
    cudaGetSymbolAddress((void**)&w1h, g_w1_h);  cudaGetSymbolAddress((void**)&w1l, g_w1_l);
    cudaGetSymbolAddress((void**)&w2h, g_w2_h);  cudaGetSymbolAddress((void**)&w2l, g_w2_l);
    cudaGetSymbolAddress((void**)&w3h, g_w3_h);  cudaGetSymbolAddress((void**)&w3l, g_w3_l);
    cudaGetSymbolAddress((void**)&buf1, g_buf1);
    cudaGetSymbolAddress((void**)&att, g_att);
    cudaGetSymbolAddress((void**)&colsum, g_colsum);
    cudaGetSymbolAddress((void**)&sumA, g_sumA);
    cudaGetSymbolAddress((void**)&sum2A, g_sum2A);
    cudaGetSymbolAddress((void**)&sumB, g_sumB);
    cudaGetSymbolAddress((void**)&sum2B, g_sum2B);

    void* pfn = nullptr;
    cudaDriverEntryPointQueryResult qr;
    cudaGetDriverEntryPoint("cuTensorMapEncodeTiled", &pfn, cudaEnableDefault, &qr);
    EncFn enc = (EncFn)pfn;

    const uint64_t RA = (uint64_t)BB * HW;
    CUtensorMap tXh, tXl, tB1h, tB1l, tB2h, tB2l, tAth, tAtl;
    CUtensorMap tW1h, tW1l, tW2h, tW2l, tW3h, tW3l, tCth, tCtl, tCsh, tCsl;
    make_map(enc, &tXh,  xTh,  CIN, RA, 128);  make_map(enc, &tXl,  xTl,  CIN, RA, 128);
    make_map(enc, &tB1h, b1h,  COUT, RA, 128); make_map(enc, &tB1l, b1l,  COUT, RA, 128);
    make_map(enc, &tB2h, b2h,  COUT, RA, 128); make_map(enc, &tB2l, b2l,  COUT, RA, 128);
    make_map(enc, &tAth, atth, MCB, RA, 128);  make_map(enc, &tAtl, attl, MCB, RA, 128);
    make_map(enc, &tW1h, w1h,  CIN, COUT, 128); make_map(enc, &tW1l, w1l, CIN, COUT, 128);
    make_map(enc, &tW2h, w2h,  COUT, CIN, 128); make_map(enc, &tW2l, w2l, COUT, CIN, 128);
    make_map(enc, &tW3h, w3h,  CIN, CIN, 128);  make_map(enc, &tW3l, w3l, CIN, CIN, 128);
    make_map(enc, &tCth, cth,  COUT, MCB, 96);  make_map(enc, &tCtl, ctl, COUT, MCB, 96);
    make_map(enc, &tCsh, csh,  MCB, (uint64_t)BB * COUT, 128);
    make_map(enc, &tCsl, csl,  MCB, (uint64_t)BB * COUT, 128);

    const size_t S  = (size_t)HW * CIN;
    const size_t SA = (size_t)HW * MCB;

    const int SM128 = 3 * (16384 + 2 * 128 * 64);
    const int SM96  = 3 * (16384 + 2 * 96 * 64);
    cudaFuncSetAttribute(gemm_tma<128, true,  true,  false>, cudaFuncAttributeMaxDynamicSharedMemorySize, SM128);
    cudaFuncSetAttribute(gemm_tma<96,  false, false, false>, cudaFuncAttributeMaxDynamicSharedMemorySize, SM96);
    cudaFuncSetAttribute(gemm_tma<128, false, true,  false>, cudaFuncAttributeMaxDynamicSharedMemorySize, SM128);
    cudaFuncSetAttribute(gemm_tma<128, false, false, true >, cudaFuncAttributeMaxDynamicSharedMemorySize, SM128);
    cudaFuncSetAttribute(gemm_tma<128, true,  false, true >, cudaFuncAttributeMaxDynamicSharedMemorySize, SM128);

    // 0. prep
    zero_all_kernel<<<3, 1024>>>(colsum, sumA, sum2A, sumB, sum2B);
    transpose_in_split<<<dim3(HW / 32, CIN / 32, BB), dim3(32, 8)>>>(x, xTh, xTl);
    prep_split_kernel<<<(3 * COUT * CIN + COUT * MCB + 255) / 256, 256>>>(
        conv1_w, conv2_w, conv3_w, centers, w1h, w1l, w2h, w2l, w3h, w3l, cth, ctl);

    // 1. conv1 -> split b1 planes
    gemm_tma<128, true, true, false><<<dim3(4, 32, BB), 256, SM128>>>(
        tXh, tXl, tW1h, tW1l, conv1_b, nullptr, b1h, b1l, nullptr, nullptr, CIN, COUT, 0, S);

    // 2. att raw -> fp32 att
    gemm_tma<96, false, false, false><<<dim3(2, 32, BB), 256, SM96>>>(
        tB1h, tB1l, tCth, tCtl, nullptr, att, nullptr, nullptr, nullptr, nullptr, COUT, MCB, 0, SA);

    // 3. softmax (single pass) + batch-scaled centers
    softmax_colsum_split<<<dim3(HW / 256, BB), 256>>>(att, colsum, atth, attl);
    scale_centers_split<<<dim3((COUT * MCB + 255) / 256, BB), 256>>>(centers, colsum, csh, csl);

    // 4. recon = att_sm @ (scaled centers)^T -> split b2 planes
    gemm_tma<128, false, true, false><<<dim3(4, 32, BB), 256, SM128>>>(
        tAth, tAtl, tCsh, tCsl, nullptr, nullptr, b2h, b2l, nullptr, nullptr, MCB, COUT, COUT, S);

    // 5. conv2 -> fp32 buf1 (+fused BN stats -> sumA)
    gemm_tma<128, false, false, true><<<dim3(4, 32, BB), 256, SM128>>>(
        tB2h, tB2l, tW2h, tW2l, nullptr, buf1, nullptr, nullptr, sumA, sum2A, COUT, CIN, 0, S);

    // 6. BN2 apply (inline finalize) + ReLU + residual -> split b2
    bn_apply_res_split<<<(unsigned)(((size_t)BB * S / 4) / 256), 256>>>(
        buf1, xTh, xTl, sumA, sum2A, bn2_g, bn2_b, b2h, b2l);

    // 7. conv3 -> fp32 buf1 (+fused BN stats -> sumB)
    gemm_tma<128, true, false, true><<<dim3(4, 32, BB), 256, SM128>>>(
        tB2h, tB2l, tW3h, tW3l, conv3_b, buf1, nullptr, nullptr, sumB, sum2B, CIN, CIN, 0, S);

    // 8. BN3 apply (inline finalize) + ReLU + transpose -> out
    bn_apply_transpose_kernel<<<dim3(HW / 32, CIN / 32, BB), dim3(32, 8)>>>(
        buf1, sumB, sum2B, bn3_g, bn3_b, out);
}

// round 15
// speedup vs baseline: 1.3920x; 1.3920x over previous
#include <cuda.h>
#include <cuda_runtime.h>
#include <cuda_bf16.h>
#include <cuda_fp16.h>
#include <math.h>
#include <stdint.h>

// ---------------- problem constants ----------------
#define BB   16
#define CIN  512
#define COUT 512
#define HW   4096
#define MCB  192
#define EPS_BN 1e-5f
#define BK   32

typedef __half f16;

#define SWZ(o) ((o) ^ (((o) >> 3) & 0x30))

// ---------------- scratch (device globals) ----------------
__device__ f16   g_xT  [(size_t)BB * HW * CIN];     // activations: single fp16 plane
__device__ f16   g_b1  [(size_t)BB * HW * COUT];
__device__ f16   g_b2  [(size_t)BB * HW * CIN];
__device__ f16   g_att16[(size_t)BB * HW * MCB];
__device__ float g_buf1 [(size_t)BB * HW * COUT];
__device__ float g_att  [(size_t)BB * HW * MCB];
__device__ f16   g_ct_h [MCB * COUT];               // weights/centers: 2-plane fp16
__device__ f16   g_ct_l [MCB * COUT];
__device__ f16   g_cs_h [(size_t)BB * COUT * MCB];
__device__ f16   g_cs_l [(size_t)BB * COUT * MCB];
__device__ f16   g_w1_h [COUT * CIN];
__device__ f16   g_w1_l [COUT * CIN];
__device__ f16   g_w2_h [CIN * COUT];
__device__ f16   g_w2_l [CIN * COUT];
__device__ f16   g_w3_h [CIN * CIN];
__device__ f16   g_w3_l [CIN * CIN];
__device__ float g_colsum[BB * MCB];
__device__ float g_sumA [CIN];
__device__ float g_sum2A[CIN];
__device__ float g_sumB [CIN];
__device__ float g_sum2B[CIN];

// ---------------- device helpers ----------------
__device__ __forceinline__ uint32_t smem_u32(const void* p) {
    uint32_t a;
    asm("{ .reg .u64 t; cvta.to.shared.u64 t, %1; cvt.u32.u64 %0, t; }" : "=r"(a) : "l"(p));
    return a;
}
__device__ __forceinline__ void ldmatrix_x4(uint32_t& r0, uint32_t& r1, uint32_t& r2, uint32_t& r3, uint32_t addr) {
    asm volatile("ldmatrix.sync.aligned.m8n8.x4.shared.b16 {%0,%1,%2,%3}, [%4];"
                 : "=r"(r0), "=r"(r1), "=r"(r2), "=r"(r3) : "r"(addr));
}
__device__ __forceinline__ void ldmatrix_x2(uint32_t& r0, uint32_t& r1, uint32_t addr) {
    asm volatile("ldmatrix.sync.aligned.m8n8.x2.shared.b16 {%0,%1}, [%2];"
                 : "=r"(r0), "=r"(r1) : "r"(addr));
}
__device__ __forceinline__ void mma_f16(float* c, uint32_t a0, uint32_t a1, uint32_t a2, uint32_t a3,
                                        uint32_t b0, uint32_t b1) {
    asm("mma.sync.aligned.m16n8k16.row.col.f32.f16.f16.f32 "
        "{%0,%1,%2,%3}, {%4,%5,%6,%7}, {%8,%9}, {%0,%1,%2,%3};"
        : "+f"(c[0]), "+f"(c[1]), "+f"(c[2]), "+f"(c[3])
        : "r"(a0), "r"(a1), "r"(a2), "r"(a3), "r"(b0), "r"(b1));
}
__device__ __forceinline__ uint32_t pack_h2(float x, float y) {
    __half2 h = __floats2half2_rn(x, y);
    return *(uint32_t*)&h;
}
__device__ __forceinline__ void splitw(float v, f16& h, f16& l) {
    h = __float2half_rn(v);
    l = __float2half_rn(v - __half2float(h));
}

#define MBARRIER_INIT(addr, cnt) \
    asm volatile("mbarrier.init.shared.b64 [%0], %1;" :: "r"((uint32_t)(addr)), "r"((uint32_t)(cnt)) : "memory")
#define MBARRIER_EXPECT_TX(addr, tx) \
    asm volatile("mbarrier.arrive.expect_tx.shared.b64 _, [%0], %1;" :: "r"((uint32_t)(addr)), "r"((uint32_t)(tx)) : "memory")
#define MBARRIER_ARRIVE(addr) \
    asm volatile("mbarrier.arrive.shared.b64 _, [%0];" :: "r"((uint32_t)(addr)) : "memory")
#define MBARRIER_WAIT_PARITY(addr, par) do { \
    uint32_t _m = (uint32_t)(addr); uint32_t _p = (uint32_t)(par); uint32_t _d; \
    asm volatile("{\n\t.reg .pred p;\n\tmbarrier.try_wait.parity.acquire.cta.shared::cta.b64 p, [%1], %2;\n\tselp.b32 %0, 1, 0, p;\n\t}" \
        : "=r"(_d) : "r"(_m), "r"(_p) : "memory"); \
    if (!_d) { \
        asm volatile("{\n\t.reg .pred P1;\n\tWL_%=:\n\tmbarrier.try_wait.parity.acquire.cta.shared::cta.b64 P1, [%0], %1, 0x989680;\n\t@P1 bra.uni WD_%=;\n\tbra.uni WL_%=;\n\tWD_%=:\n\t}" \
            :: "r"(_m), "r"(_p) : "memory"); \
    } } while (0)
#define TMA2D(dst, map, cx, cy, bar) \
    asm volatile("cp.async.bulk.tensor.2d.shared::cta.global.tile.mbarrier::complete_tx::bytes " \
                 "[%0], [%1, {%2, %3}], [%4];" \
        :: "r"((uint32_t)(dst)), "l"(map), "r"((int)(cx)), "r"((int)(cy)), "r"((uint32_t)(bar)) : "memory")

// ---------------- fp16 2-term GEMM, 3-stage TMA pipeline ----------------
// C[m,n] = sum_k A[m,k]*(Bh[n,k]+Bl[n,k]) (+bias[n]).
// A single fp16 plane; B 2-plane fp16 (exact weights).
template<int NT, bool BIAS, bool F16OUT, bool BNSTAT>
__global__ __launch_bounds__(256, 2)
void gemm_tma(const __grid_constant__ CUtensorMap mA,
              const __grid_constant__ CUtensorMap mBh,
              const __grid_constant__ CUtensorMap mBl,
              const float* __restrict__ bias,
              float* __restrict__ Cf, f16* __restrict__ Cp,
              float* __restrict__ gsum, float* __restrict__ gsum2,
              int Kd, int Ntot, int bZmul, size_t cS)
{
    constexpr int WN = NT / 4;
    constexpr int NF = WN / 8;
    constexpr int OFF_BH = 8192;
    constexpr int OFF_BL = 8192 + NT * 64;
    constexpr int STAGE  = 8192 + 2 * NT * 64;   // 24576 (NT=128) / 20480 (NT=96)

    extern __shared__ __align__(1024) char dsm[];
    __shared__ __align__(8) uint64_t mbar_full[3];
    __shared__ __align__(8) uint64_t mbar_empty[3];
    __shared__ float bn_s[NT];
    __shared__ float bn_s2[NT];

    const uint32_t sbase = smem_u32(dsm);
    const int tid = threadIdx.x;
    const int lane = tid & 31;
    const int wid = tid >> 5;
    const int wm = wid & 1;
    const int wn = wid >> 1;
    const int m0 = blockIdx.y * 128;
    const int n0 = blockIdx.x * NT;
    const int z  = blockIdx.z;

    const int NC = Kd / BK;
    const int cyA = z * HW + m0;
    const int cyB = z * bZmul + n0;

    if (tid == 0) {
#pragma unroll
        for (int s = 0; s < 3; ++s) {
            MBARRIER_INIT(smem_u32(&mbar_full[s]), 1);
            MBARRIER_INIT(smem_u32(&mbar_empty[s]), 8);
        }
    }
    __syncthreads();

    auto issue = [&](int i) {
        const int s = i % 3;
        const uint32_t bar = smem_u32(&mbar_full[s]);
        const uint32_t st = sbase + s * STAGE;
        MBARRIER_EXPECT_TX(bar, (uint32_t)STAGE);
        const int cx = i * BK;
        TMA2D(st,          &mA,  cx, cyA, bar);
        TMA2D(st + OFF_BH, &mBh, cx, cyB, bar);
        TMA2D(st + OFF_BL, &mBl, cx, cyB, bar);
    };
    if (tid == 0) { issue(0); issue(1); issue(2); }

    float acc[4][NF][4];
#pragma unroll
    for (int mi = 0; mi < 4; ++mi)
#pragma unroll
        for (int ni = 0; ni < NF; ++ni)
#pragma unroll
            for (int j = 0; j < 4; ++j) acc[mi][ni][j] = 0.f;

    const int arow = wm * 64;
    const int brow = wn * WN;
    const int l7 = lane & 7;
    const int aq = lane >> 3;
    const int arsel = (aq & 1) * 8;
    const int acsel = (aq >> 1) * 16;
    const int b4r = ((lane >> 4) & 1) * 8;
    const int b4c = ((lane >> 3) & 1) * 16;
    const int b2c = ((lane >> 3) & 1) * 16;

    for (int i = 0; i < NC; ++i) {
        const int s = i % 3;
        const int par = (i / 3) & 1;
        MBARRIER_WAIT_PARITY(smem_u32(&mbar_full[s]), par);

        const uint32_t st = sbase + s * STAGE;
        const uint32_t sA  = st;
        const uint32_t sBh = st + OFF_BH;
        const uint32_t sBl = st + OFF_BL;

#pragma unroll
        for (int k16 = 0; k16 < 2; ++k16) {
            const int kb = k16 * 32;
            uint32_t bh[NF][2], bl[NF][2];
#pragma unroll
            for (int p = 0; p < NF / 2; ++p) {
                uint32_t bo = SWZ((uint32_t)((brow + p * 16 + b4r + l7) * 64 + kb + b4c));
                ldmatrix_x4(bh[2*p][0], bh[2*p][1], bh[2*p+1][0], bh[2*p+1][1], sBh + bo);
                ldmatrix_x4(bl[2*p][0], bl[2*p][1], bl[2*p+1][0], bl[2*p+1][1], sBl + bo);
            }
            if (NF & 1) {
                const int ni = NF - 1;
                uint32_t bo = SWZ((uint32_t)((brow + ni * 8 + l7) * 64 + kb + b2c));
                ldmatrix_x2(bh[ni][0], bh[ni][1], sBh + bo);
                ldmatrix_x2(bl[ni][0], bl[ni][1], sBl + bo);
            }
#pragma unroll
            for (int mi = 0; mi < 4; ++mi) {
                uint32_t ao = SWZ((uint32_t)((arow + mi * 16 + arsel + l7) * 64 + kb + acsel));
                uint32_t a0, a1, a2, a3;
                ldmatrix_x4(a0, a1, a2, a3, sA + ao);
#pragma unroll
                for (int ni = 0; ni < NF; ++ni)
                    mma_f16(acc[mi][ni], a0, a1, a2, a3, bh[ni][0], bh[ni][1]);
#pragma unroll
                for (int ni = 0; ni < NF; ++ni)
                    mma_f16(acc[mi][ni], a0, a1, a2, a3, bl[ni][0], bl[ni][1]);
            }
        }

        if (lane == 0) MBARRIER_ARRIVE(smem_u32(&mbar_empty[s]));
        if (tid == 0 && i + 3 < NC) {
            MBARRIER_WAIT_PARITY(smem_u32(&mbar_empty[s]), par);
            issue(i + 3);
        }
    }

    // ---- epilogue ----
    const int l4 = lane >> 2;
    const int lc = (lane & 3) * 2;
    float ps0[NF], ps1[NF], q0s[NF], q1s[NF];
#pragma unroll
    for (int ni = 0; ni < NF; ++ni) { ps0[ni] = ps1[ni] = q0s[ni] = q1s[ni] = 0.f; }

#pragma unroll
    for (int mi = 0; mi < 4; ++mi) {
        const int row = m0 + wm * 64 + mi * 16 + l4;
#pragma unroll
        for (int ni = 0; ni < NF; ++ni) {
            const int col = n0 + wn * WN + ni * 8 + lc;
            float b0 = BIAS ? bias[col] : 0.f;
            float b1 = BIAS ? bias[col + 1] : 0.f;
            float v00 = acc[mi][ni][0] + b0, v01 = acc[mi][ni][1] + b1;
            float v10 = acc[mi][ni][2] + b0, v11 = acc[mi][ni][3] + b1;
            if (BNSTAT) {
                ps0[ni] += v00 + v10;  q0s[ni] += v00 * v00 + v10 * v10;
                ps1[ni] += v01 + v11;  q1s[ni] += v01 * v01 + v11 * v11;
            }
            if (F16OUT) {
                size_t o0 = (size_t)z * cS + (size_t)row * Ntot + col;
                size_t o1 = (size_t)z * cS + (size_t)(row + 8) * Ntot + col;
                *(uint32_t*)(Cp + o0) = pack_h2(v00, v01);
                *(uint32_t*)(Cp + o1) = pack_h2(v10, v11);
            } else {
                float* C = Cf + (size_t)z * cS;
                float2 w0 = { v00, v01 };
                float2 w1 = { v10, v11 };
                *(float2*)(C + (size_t)row * Ntot + col) = w0;
                *(float2*)(C + (size_t)(row + 8) * Ntot + col) = w1;
            }
        }
    }

    if (BNSTAT) {
        __syncthreads();
        for (int t = tid; t < NT; t += 256) { bn_s[t] = 0.f; bn_s2[t] = 0.f; }
        __syncthreads();
#pragma unroll
        for (int ni = 0; ni < NF; ++ni) {
            float a = ps0[ni], b = ps1[ni], c = q0s[ni], d = q1s[ni];
#pragma unroll
            for (int o = 4; o <= 16; o <<= 1) {
                a += __shfl_xor_sync(0xffffffffu, a, o);
                b += __shfl_xor_sync(0xffffffffu, b, o);
                c += __shfl_xor_sync(0xffffffffu, c, o);
                d += __shfl_xor_sync(0xffffffffu, d, o);
            }
            if (lane < 4) {
                int cl = wn * WN + ni * 8 + lc;
                atomicAdd(&bn_s[cl], a);  atomicAdd(&bn_s[cl + 1], b);
                atomicAdd(&bn_s2[cl], c); atomicAdd(&bn_s2[cl + 1], d);
            }
        }
        __syncthreads();
        for (int t = tid; t < NT; t += 256) {
            atomicAdd(&gsum[n0 + t], bn_s[t]);
            atomicAdd(&gsum2[n0 + t], bn_s2[t]);
        }
    }
}

// ---------------- prep kernels ----------------
__global__ void zero_all_kernel(float* cs, float* sA, float* s2A, float* sB, float* s2B)
{
    int i = blockIdx.x * 1024 + threadIdx.x;
    if (i < BB * MCB) cs[i] = 0.f;
    if (i < CIN) { sA[i] = 0.f; s2A[i] = 0.f; sB[i] = 0.f; s2B[i] = 0.f; }
}

__global__ void prep_split_kernel(const float* __restrict__ w1, const float* __restrict__ w2,
                                  const float* __restrict__ w3, const float* __restrict__ cen,
                                  f16* __restrict__ w1h, f16* __restrict__ w1l,
                                  f16* __restrict__ w2h, f16* __restrict__ w2l,
                                  f16* __restrict__ w3h, f16* __restrict__ w3l,
                                  f16* __restrict__ cth, f16* __restrict__ ctl)
{
    const int W = COUT * CIN;
    const int CT = COUT * MCB;
    int i = blockIdx.x * 256 + threadIdx.x;
    f16 hh, ll;
    if (i < W) {
        splitw(w1[i], hh, ll); w1h[i] = hh; w1l[i] = ll;
    } else if (i < 2 * W) {
        int j = i - W;
        splitw(w2[j], hh, ll); w2h[j] = hh; w2l[j] = ll;
    } else if (i < 3 * W) {
        int j = i - 2 * W;
        splitw(w3[j], hh, ll); w3h[j] = hh; w3l[j] = ll;
    } else if (i < 3 * W + CT) {
        int j = i - 3 * W;
        int c = j / MCB, k = j % MCB;
        splitw(cen[j], hh, ll);
        cth[k * COUT + c] = hh; ctl[k * COUT + c] = ll;
    }
}

__global__ void transpose_in_f16(const float* __restrict__ in, f16* __restrict__ o)
{
    __shared__ float t[32][33];
    const int b = blockIdx.z;
    const int n0 = blockIdx.x * 32, c0 = blockIdx.y * 32;
    const float* ip = in + (size_t)b * CIN * HW;
#pragma unroll
    for (int i = 0; i < 32; i += 8)
        t[threadIdx.y + i][threadIdx.x] = ip[(size_t)(c0 + threadIdx.y + i) * HW + n0 + threadIdx.x];
    __syncthreads();
#pragma unroll
    for (int i = 0; i < 32; i += 8) {
        float v = t[threadIdx.x][threadIdx.y + i];
        size_t oo = (size_t)b * HW * CIN + (size_t)(n0 + threadIdx.y + i) * CIN + c0 + threadIdx.x;
        o[oo] = __float2half_rn(v);
    }
}

__global__ void scale_centers_split(const float* __restrict__ centers, const float* __restrict__ colsum,
                                    f16* __restrict__ oh, f16* __restrict__ ol)
{
    int i = blockIdx.x * 256 + threadIdx.x;
    int b = blockIdx.y;
    if (i < COUT * MCB) {
        int k = i % MCB;
        float r = 1.f / (1e-6f + colsum[b * MCB + k]);
        float v = centers[i] * r;
        f16 hh, ll;
        splitw(v, hh, ll);
        size_t o = (size_t)b * COUT * MCB + i;
        oh[o] = hh; ol[o] = ll;
    }
}

// ---------------- softmax: single pass, fp16 out + colsum ----------------
__global__ void softmax_colsum_f16(const float* __restrict__ att, float* __restrict__ colsum,
                                   f16* __restrict__ o)
{
    const int warp = threadIdx.x >> 5;
    const int lane = threadIdx.x & 31;
    const int b = blockIdx.y;
    const int rowBase = blockIdx.x * 256 + warp * 32;
    float cacc[6] = {0.f, 0.f, 0.f, 0.f, 0.f, 0.f};

    for (int r = 0; r < 32; ++r) {
        const int n = rowBase + r;
        const size_t base = ((size_t)b * HW + n) * MCB;
        const float* p = att + base;
        float v[6];
        float mx = -1e30f;
#pragma unroll
        for (int j = 0; j < 6; ++j) { v[j] = p[j * 32 + lane]; mx = fmaxf(mx, v[j]); }
#pragma unroll
        for (int o2 = 16; o2 > 0; o2 >>= 1) mx = fmaxf(mx, __shfl_xor_sync(0xffffffffu, mx, o2));
        float s = 0.f;
#pragma unroll
        for (int j = 0; j < 6; ++j) { v[j] = expf(v[j] - mx); s += v[j]; }
#pragma unroll
        for (int o2 = 16; o2 > 0; o2 >>= 1) s += __shfl_xor_sync(0xffffffffu, s, o2);
        const float inv = 1.f / s;
#pragma unroll
        for (int j = 0; j < 6; ++j) {
            float ov = v[j] * inv;
            cacc[j] += ov;
            o[base + j * 32 + lane] = __float2half_rn(ov);
        }
    }
#pragma unroll
    for (int j = 0; j < 6; ++j)
        atomicAdd(&colsum[b * MCB + j * 32 + lane], cacc[j]);
}

// ---------------- BN apply (inline finalize) ----------------
__global__ void bn_apply_res_f16(const float* __restrict__ t,
                                 const f16* __restrict__ x16,
                                 const float* __restrict__ gsum, const float* __restrict__ gsum2,
                                 const float* __restrict__ gamma, const float* __restrict__ beta,
                                 f16* __restrict__ o)
{
    size_t i = (size_t)blockIdx.x * blockDim.x + threadIdx.x;   // float4 index
    const int c4 = (int)(i & 127);
    const float N = (float)((size_t)BB * HW);
    const float4 sm = ((const float4*)gsum)[c4];
    const float4 s2 = ((const float4*)gsum2)[c4];
    const float4 gm = ((const float4*)gamma)[c4];
    const float4 bt = ((const float4*)beta)[c4];
    float4 sc, sh;
    {
        float m, vr;
        m = sm.x / N; vr = s2.x / N - m * m; sc.x = gm.x * rsqrtf(vr + EPS_BN); sh.x = bt.x - m * sc.x;
        m = sm.y / N; vr = s2.y / N - m * m; sc.y = gm.y * rsqrtf(vr + EPS_BN); sh.y = bt.y - m * sc.y;
        m = sm.z / N; vr = s2.z / N - m * m; sc.z = gm.z * rsqrtf(vr + EPS_BN); sh.z = bt.z - m * sc.z;
        m = sm.w / N; vr = s2.w / N - m * m; sc.w = gm.w * rsqrtf(vr + EPS_BN); sh.w = bt.w - m * sc.w;
    }
    float4 v = ((const float4*)t)[i];
    uint2 xu = *(const uint2*)(x16 + i * 4);
    __half2 x0 = *(__half2*)&xu.x;
    __half2 x1 = *(__half2*)&xu.y;
    float r0, r1, r2, r3;
    r0 = fmaxf(fmaf(sc.x, v.x, sh.x), 0.f) + __half2float(x0.x);
    r1 = fmaxf(fmaf(sc.y, v.y, sh.y), 0.f) + __half2float(x0.y);
    r2 = fmaxf(fmaf(sc.z, v.z, sh.z), 0.f) + __half2float(x1.x);
    r3 = fmaxf(fmaf(sc.w, v.w, sh.w), 0.f) + __half2float(x1.y);
    uint2 ou = { pack_h2(r0, r1), pack_h2(r2, r3) };
    *(uint2*)(o + i * 4) = ou;
}

__global__ void bn_apply_transpose_kernel(const float* __restrict__ in,
                                          const float* __restrict__ gsum, const float* __restrict__ gsum2,
                                          const float* __restrict__ gamma, const float* __restrict__ beta,
                                          float* __restrict__ out)
{
    __shared__ float t[32][33];
    const int b = blockIdx.z;
    const int n0 = blockIdx.x * 32, c0 = blockIdx.y * 32;
    const float* ip = in + (size_t)b * HW * CIN;
    float* op = out + (size_t)b * CIN * HW;
    const int c = c0 + threadIdx.x;
    const float N = (float)((size_t)BB * HW);
    const float mean = gsum[c] / N;
    const float var = gsum2[c] / N - mean * mean;
    const float sc = gamma[c] * rsqrtf(var + EPS_BN);
    const float sh = beta[c] - mean * sc;
#pragma unroll
    for (int i = 0; i < 32; i += 8) {
        float v = ip[(size_t)(n0 + threadIdx.y + i) * CIN + c];
        t[threadIdx.y + i][threadIdx.x] = fmaxf(fmaf(sc, v, sh), 0.f);
    }
    __syncthreads();
#pragma unroll
    for (int i = 0; i < 32; i += 8)
        op[(size_t)(c0 + threadIdx.y + i) * HW + n0 + threadIdx.x] = t[threadIdx.x][threadIdx.y + i];
}

// ---------------- host-side tensor map helper ----------------
typedef CUresult (*EncFn)(CUtensorMap*, CUtensorMapDataType, cuuint32_t, void*,
                          const cuuint64_t*, const cuuint64_t*, const cuuint32_t*, const cuuint32_t*,
                          CUtensorMapInterleave, CUtensorMapSwizzle, CUtensorMapL2promotion,
                          CUtensorMapFloatOOBfill);

static void make_map(EncFn enc, CUtensorMap* m, void* base, uint64_t kd, uint64_t rows, uint32_t box_rows)
{
    cuuint64_t dims[2] = { kd, rows };
    cuuint64_t strides[1] = { kd * 2 };
    cuuint32_t box[2] = { 32, box_rows };
    cuuint32_t es[2] = { 1, 1 };
    enc(m, CU_TENSOR_MAP_DATA_TYPE_FLOAT16, 2, base, dims, strides, box, es,
        CU_TENSOR_MAP_INTERLEAVE_NONE, CU_TENSOR_MAP_SWIZZLE_64B,
        CU_TENSOR_MAP_L2_PROMOTION_L2_128B, CU_TENSOR_MAP_FLOAT_OOB_FILL_NONE);
}

// ---------------- launch ----------------
extern "C" void kernel_launch(void* const* d_in, const int* in_sizes, int n_in,
                              void* d_out, int out_size)
{
    const float* x       = (const float*)d_in[0];
    const float* centers = (const float*)d_in[1];
    const float* conv1_w = (const float*)d_in[2];
    const float* conv1_b = (const float*)d_in[3];
    const float* conv2_w = (const float*)d_in[4];
    const float* bn2_g   = (const float*)d_in[5];
    const float* bn2_b   = (const float*)d_in[6];
    const float* conv3_w = (const float*)d_in[7];
    const float* conv3_b = (const float*)d_in[8];
    const float* bn3_g   = (const float*)d_in[9];
    const float* bn3_b   = (const float*)d_in[10];
    float* out = (float*)d_out;

    f16 *xT, *b1, *b2, *att16, *cth, *ctl, *csh, *csl;
    f16 *w1h, *w1l, *w2h, *w2l, *w3h, *w3l;
    float *buf1, *att, *colsum, *sumA, *sum2A, *sumB, *sum2B;
    cudaGetSymbolAddress((void**)&xT, g_xT);
    cudaGetSymbolAddress((void**)&b1, g_b1);
    cudaGetSymbolAddress((void**)&b2, g_b2);
    cudaGetSymbolAddress((void**)&att16, g_att16);
    cudaGetSymbolAddress((void**)&cth, g_ct_h);  cudaGetSymbolAddress((void**)&ctl, g_ct_l);
    cudaGetSymbolAddress((void**)&csh, g_cs_h);  cudaGetSymbolAddress((void**)&csl, g_cs_l);
    cudaGetSymbolAddress((void**)&w1h, g_w1_h);  cudaGetSymbolAddress((void**)&w1l, g_w1_l);
    cudaGetSymbolAddress((void**)&w2h, g_w2_h);  cudaGetSymbolAddress((void**)&w2l, g_w2_l);
    cudaGetSymbolAddress((void**)&w3h, g_w3_h);  cudaGetSymbolAddress((void**)&w3l, g_w3_l);
    cudaGetSymbolAddress((void**)&buf1, g_buf1);
    cudaGetSymbolAddress((void**)&att, g_att);
    cudaGetSymbolAddress((void**)&colsum, g_colsum);
    cudaGetSymbolAddress((void**)&sumA, g_sumA);
    cudaGetSymbolAddress((void**)&sum2A, g_sum2A);
    cudaGetSymbolAddress((void**)&sumB, g_sumB);
    cudaGetSymbolAddress((void**)&sum2B, g_sum2B);

    void* pfn = nullptr;
    cudaDriverEntryPointQueryResult qr;
    cudaGetDriverEntryPoint("cuTensorMapEncodeTiled", &pfn, cudaEnableDefault, &qr);
    EncFn enc = (EncFn)pfn;

    const uint64_t RA = (uint64_t)BB * HW;
    CUtensorMap tX, tB1, tB2, tAtt;
    CUtensorMap tW1h, tW1l, tW2h, tW2l, tW3h, tW3l, tCth, tCtl, tCsh, tCsl;
    make_map(enc, &tX,   xT,   CIN, RA, 128);
    make_map(enc, &tB1,  b1,   COUT, RA, 128);
    make_map(enc, &tB2,  b2,   COUT, RA, 128);
    make_map(enc, &tAtt, att16, MCB, RA, 128);
    make_map(enc, &tW1h, w1h,  CIN, COUT, 128); make_map(enc, &tW1l, w1l, CIN, COUT, 128);
    make_map(enc, &tW2h, w2h,  COUT, CIN, 128); make_map(enc, &tW2l, w2l, COUT, CIN, 128);
    make_map(enc, &tW3h, w3h,  CIN, CIN, 128);  make_map(enc, &tW3l, w3l, CIN, CIN, 128);
    make_map(enc, &tCth, cth,  COUT, MCB, 96);  make_map(enc, &tCtl, ctl, COUT, MCB, 96);
    make_map(enc, &tCsh, csh,  MCB, (uint64_t)BB * COUT, 128);
    make_map(enc, &tCsl, csl,  MCB, (uint64_t)BB * COUT, 128);

    const size_t S  = (size_t)HW * CIN;
    const size_t SA = (size_t)HW * MCB;

    const int SM128 = 3 * (8192 + 2 * 128 * 64);   // 73728
    const int SM96  = 3 * (8192 + 2 * 96 * 64);    // 61440
    cudaFuncSetAttribute(gemm_tma<128, true,  true,  false>, cudaFuncAttributeMaxDynamicSharedMemorySize, SM128);
    cudaFuncSetAttribute(gemm_tma<96,  false, false, false>, cudaFuncAttributeMaxDynamicSharedMemorySize, SM96);
    cudaFuncSetAttribute(gemm_tma<128, false, true,  false>, cudaFuncAttributeMaxDynamicSharedMemorySize, SM128);
    cudaFuncSetAttribute(gemm_tma<128, false, false, true >, cudaFuncAttributeMaxDynamicSharedMemorySize, SM128);
    cudaFuncSetAttribute(gemm_tma<128, true,  false, true >, cudaFuncAttributeMaxDynamicSharedMemorySize, SM128);

    // 0. prep
    zero_all_kernel<<<3, 1024>>>(colsum, sumA, sum2A, sumB, sum2B);
    transpose_in_f16<<<dim3(HW / 32, CIN / 32, BB), dim3(32, 8)>>>(x, xT);
    prep_split_kernel<<<(3 * COUT * CIN + COUT * MCB + 255) / 256, 256>>>(
        conv1_w, conv2_w, conv3_w, centers, w1h, w1l, w2h, w2l, w3h, w3l, cth, ctl);

    // 1. conv1 -> fp16 b1
    gemm_tma<128, true, true, false><<<dim3(4, 32, BB), 256, SM128>>>(
        tX, tW1h, tW1l, conv1_b, nullptr, b1, nullptr, nullptr, CIN, COUT, 0, S);

    // 2. att raw -> fp32 att
    gemm_tma<96, false, false, false><<<dim3(2, 32, BB), 256, SM96>>>(
        tB1, tCth, tCtl, nullptr, att, nullptr, nullptr, nullptr, COUT, MCB, 0, SA);

    // 3. softmax (single pass, fp16 out) + batch-scaled centers
    softmax_colsum_f16<<<dim3(HW / 256, BB), 256>>>(att, colsum, att16);
    scale_centers_split<<<dim3((COUT * MCB + 255) / 256, BB), 256>>>(centers, colsum, csh, csl);

    // 4. recon = att_sm @ (scaled centers)^T -> fp16 b2
    gemm_tma<128, false, true, false><<<dim3(4, 32, BB), 256, SM128>>>(
        tAtt, tCsh, tCsl, nullptr, nullptr, b2, nullptr, nullptr, MCB, COUT, COUT, S);

    // 5. conv2 -> fp32 buf1 (+fused BN stats -> sumA)
    gemm_tma<128, false, false, true><<<dim3(4, 32, BB), 256, SM128>>>(
        tB2, tW2h, tW2l, nullptr, buf1, nullptr, sumA, sum2A, COUT, CIN, 0, S);

    // 6. BN2 apply (inline finalize) + ReLU + residual -> fp16 b2
    bn_apply_res_f16<<<(unsigned)(((size_t)BB * S / 4) / 256), 256>>>(
        buf1, xT, sumA, sum2A, bn2_g, bn2_b, b2);

    // 7. conv3 -> fp32 buf1 (+fused BN stats -> sumB)
    gemm_tma<128, true, false, true><<<dim3(4, 32, BB), 256, SM128>>>(
        tB2, tW3h, tW3l, conv3_b, buf1, nullptr, sumB, sum2B, CIN, CIN, 0, S);

    // 8. BN3 apply (inline finalize) + ReLU + transpose -> out
    bn_apply_transpose_kernel<<<dim3(HW / 32, CIN / 32, BB), dim3(32, 8)>>>(
        buf1, sumB, sum2B, bn3_g, bn3_b, out);
}

// round 16
// speedup vs baseline: 1.8837x; 1.3533x over previous
#include <cuda.h>
#include <cuda_runtime.h>
#include <cuda_bf16.h>
#include <cuda_fp16.h>
#include <math.h>
#include <stdint.h>

// ---------------- problem constants ----------------
#define BB   16
#define CIN  512
#define COUT 512
#define HW   4096
#define MCB  192
#define EPS_BN 1e-5f
#define BK   32

typedef __half f16;

#define SWZ(o) ((o) ^ (((o) >> 3) & 0x30))

// ---------------- scratch (device globals) ----------------
__device__ f16   g_xT  [(size_t)BB * HW * CIN];
__device__ f16   g_b1  [(size_t)BB * HW * COUT];
__device__ f16   g_b2  [(size_t)BB * HW * CIN];
__device__ f16   g_att16[(size_t)BB * HW * MCB];
__device__ float g_buf1 [(size_t)BB * HW * COUT];
__device__ float g_att  [(size_t)BB * HW * MCB];
__device__ f16   g_ct  [MCB * COUT];
__device__ f16   g_cs  [(size_t)BB * COUT * MCB];
__device__ f16   g_w1  [COUT * CIN];
__device__ f16   g_w2  [CIN * COUT];
__device__ f16   g_w3  [CIN * CIN];
__device__ float g_colsum[BB * MCB];
__device__ float g_sumA [CIN];
__device__ float g_sum2A[CIN];
__device__ float g_sumB [CIN];
__device__ float g_sum2B[CIN];

// ---------------- device helpers ----------------
__device__ __forceinline__ uint32_t smem_u32(const void* p) {
    uint32_t a;
    asm("{ .reg .u64 t; cvta.to.shared.u64 t, %1; cvt.u32.u64 %0, t; }" : "=r"(a) : "l"(p));
    return a;
}
__device__ __forceinline__ void ldmatrix_x4(uint32_t& r0, uint32_t& r1, uint32_t& r2, uint32_t& r3, uint32_t addr) {
    asm volatile("ldmatrix.sync.aligned.m8n8.x4.shared.b16 {%0,%1,%2,%3}, [%4];"
                 : "=r"(r0), "=r"(r1), "=r"(r2), "=r"(r3) : "r"(addr));
}
__device__ __forceinline__ void ldmatrix_x2(uint32_t& r0, uint32_t& r1, uint32_t addr) {
    asm volatile("ldmatrix.sync.aligned.m8n8.x2.shared.b16 {%0,%1}, [%2];"
                 : "=r"(r0), "=r"(r1) : "r"(addr));
}
__device__ __forceinline__ void mma_f16(float* c, uint32_t a0, uint32_t a1, uint32_t a2, uint32_t a3,
                                        uint32_t b0, uint32_t b1) {
    asm("mma.sync.aligned.m16n8k16.row.col.f32.f16.f16.f32 "
        "{%0,%1,%2,%3}, {%4,%5,%6,%7}, {%8,%9}, {%0,%1,%2,%3};"
        : "+f"(c[0]), "+f"(c[1]), "+f"(c[2]), "+f"(c[3])
        : "r"(a0), "r"(a1), "r"(a2), "r"(a3), "r"(b0), "r"(b1));
}
__device__ __forceinline__ uint32_t pack_h2(float x, float y) {
    __half2 h = __floats2half2_rn(x, y);
    return *(uint32_t*)&h;
}

#define MBARRIER_INIT(addr, cnt) \
    asm volatile("mbarrier.init.shared.b64 [%0], %1;" :: "r"((uint32_t)(addr)), "r"((uint32_t)(cnt)) : "memory")
#define MBARRIER_EXPECT_TX(addr, tx) \
    asm volatile("mbarrier.arrive.expect_tx.shared.b64 _, [%0], %1;" :: "r"((uint32_t)(addr)), "r"((uint32_t)(tx)) : "memory")
#define MBARRIER_ARRIVE(addr) \
    asm volatile("mbarrier.arrive.shared.b64 _, [%0];" :: "r"((uint32_t)(addr)) : "memory")
#define MBARRIER_WAIT_PARITY(addr, par) do { \
    uint32_t _m = (uint32_t)(addr); uint32_t _p = (uint32_t)(par); uint32_t _d; \
    asm volatile("{\n\t.reg .pred p;\n\tmbarrier.try_wait.parity.acquire.cta.shared::cta.b64 p, [%1], %2;\n\tselp.b32 %0, 1, 0, p;\n\t}" \
        : "=r"(_d) : "r"(_m), "r"(_p) : "memory"); \
    if (!_d) { \
        asm volatile("{\n\t.reg .pred P1;\n\tWL_%=:\n\tmbarrier.try_wait.parity.acquire.cta.shared::cta.b64 P1, [%0], %1, 0x989680;\n\t@P1 bra.uni WD_%=;\n\tbra.uni WL_%=;\n\tWD_%=:\n\t}" \
            :: "r"(_m), "r"(_p) : "memory"); \
    } } while (0)
#define TMA2D(dst, map, cx, cy, bar) \
    asm volatile("cp.async.bulk.tensor.2d.shared::cta.global.tile.mbarrier::complete_tx::bytes " \
                 "[%0], [%1, {%2, %3}], [%4];" \
        :: "r"((uint32_t)(dst)), "l"(map), "r"((int)(cx)), "r"((int)(cy)), "r"((uint32_t)(bar)) : "memory")

// ---------------- one-term fp16 GEMM, 3-stage TMA pipeline ----------------
// C[m,n] = sum_k A[m,k]*B[n,k] (+bias[n]), fp32 accumulate.
template<int NT, bool BIAS, bool F16OUT, bool BNSTAT>
__global__ __launch_bounds__(256, 2)
void gemm_tma(const __grid_constant__ CUtensorMap mA,
              const __grid_constant__ CUtensorMap mB,
              const float* __restrict__ bias,
              float* __restrict__ Cf, f16* __restrict__ Cp,
              float* __restrict__ gsum, float* __restrict__ gsum2,
              int Kd, int Ntot, int bZmul, size_t cS)
{
    constexpr int WN = NT / 4;
    constexpr int NF = WN / 8;
    constexpr int OFF_B = 8192;
    constexpr int STAGE = 8192 + NT * 64;   // 16384 (NT=128) / 14336 (NT=96)

    extern __shared__ __align__(1024) char dsm[];
    __shared__ __align__(8) uint64_t mbar_full[3];
    __shared__ __align__(8) uint64_t mbar_empty[3];
    __shared__ float bn_s[NT];
    __shared__ float bn_s2[NT];

    const uint32_t sbase = smem_u32(dsm);
    const int tid = threadIdx.x;
    const int lane = tid & 31;
    const int wid = tid >> 5;
    const int wm = wid & 1;
    const int wn = wid >> 1;
    const int m0 = blockIdx.y * 128;
    const int n0 = blockIdx.x * NT;
    const int z  = blockIdx.z;

    const int NC = Kd / BK;
    const int cyA = z * HW + m0;
    const int cyB = z * bZmul + n0;

    if (tid == 0) {
#pragma unroll
        for (int s = 0; s < 3; ++s) {
            MBARRIER_INIT(smem_u32(&mbar_full[s]), 1);
            MBARRIER_INIT(smem_u32(&mbar_empty[s]), 8);
        }
    }
    __syncthreads();

    auto issue = [&](int i) {
        const int s = i % 3;
        const uint32_t bar = smem_u32(&mbar_full[s]);
        const uint32_t st = sbase + s * STAGE;
        MBARRIER_EXPECT_TX(bar, (uint32_t)STAGE);
        const int cx = i * BK;
        TMA2D(st,         &mA, cx, cyA, bar);
        TMA2D(st + OFF_B, &mB, cx, cyB, bar);
    };
    if (tid == 0) { issue(0); issue(1); issue(2); }

    float acc[4][NF][4];
#pragma unroll
    for (int mi = 0; mi < 4; ++mi)
#pragma unroll
        for (int ni = 0; ni < NF; ++ni)
#pragma unroll
            for (int j = 0; j < 4; ++j) acc[mi][ni][j] = 0.f;

    const int arow = wm * 64;
    const int brow = wn * WN;
    const int l7 = lane & 7;
    const int aq = lane >> 3;
    const int arsel = (aq & 1) * 8;
    const int acsel = (aq >> 1) * 16;
    const int b4r = ((lane >> 4) & 1) * 8;
    const int b4c = ((lane >> 3) & 1) * 16;
    const int b2c = ((lane >> 3) & 1) * 16;

    for (int i = 0; i < NC; ++i) {
        const int s = i % 3;
        const int par = (i / 3) & 1;
        MBARRIER_WAIT_PARITY(smem_u32(&mbar_full[s]), par);

        const uint32_t st = sbase + s * STAGE;
        const uint32_t sA = st;
        const uint32_t sB = st + OFF_B;

#pragma unroll
        for (int k16 = 0; k16 < 2; ++k16) {
            const int kb = k16 * 32;
            uint32_t bh[NF][2];
#pragma unroll
            for (int p = 0; p < NF / 2; ++p) {
                uint32_t bo = SWZ((uint32_t)((brow + p * 16 + b4r + l7) * 64 + kb + b4c));
                ldmatrix_x4(bh[2*p][0], bh[2*p][1], bh[2*p+1][0], bh[2*p+1][1], sB + bo);
            }
            if (NF & 1) {
                const int ni = NF - 1;
                uint32_t bo = SWZ((uint32_t)((brow + ni * 8 + l7) * 64 + kb + b2c));
                ldmatrix_x2(bh[ni][0], bh[ni][1], sB + bo);
            }
#pragma unroll
            for (int mi = 0; mi < 4; ++mi) {
                uint32_t ao = SWZ((uint32_t)((arow + mi * 16 + arsel + l7) * 64 + kb + acsel));
                uint32_t a0, a1, a2, a3;
                ldmatrix_x4(a0, a1, a2, a3, sA + ao);
#pragma unroll
                for (int ni = 0; ni < NF; ++ni)
                    mma_f16(acc[mi][ni], a0, a1, a2, a3, bh[ni][0], bh[ni][1]);
            }
        }

        if (lane == 0) MBARRIER_ARRIVE(smem_u32(&mbar_empty[s]));
        if (tid == 0 && i + 3 < NC) {
            MBARRIER_WAIT_PARITY(smem_u32(&mbar_empty[s]), par);
            issue(i + 3);
        }
    }

    // ---- epilogue ----
    const int l4 = lane >> 2;
    const int lc = (lane & 3) * 2;
    float ps0[NF], ps1[NF], q0s[NF], q1s[NF];
#pragma unroll
    for (int ni = 0; ni < NF; ++ni) { ps0[ni] = ps1[ni] = q0s[ni] = q1s[ni] = 0.f; }

#pragma unroll
    for (int mi = 0; mi < 4; ++mi) {
        const int row = m0 + wm * 64 + mi * 16 + l4;
#pragma unroll
        for (int ni = 0; ni < NF; ++ni) {
            const int col = n0 + wn * WN + ni * 8 + lc;
            float b0 = BIAS ? bias[col] : 0.f;
            float b1 = BIAS ? bias[col + 1] : 0.f;
            float v00 = acc[mi][ni][0] + b0, v01 = acc[mi][ni][1] + b1;
            float v10 = acc[mi][ni][2] + b0, v11 = acc[mi][ni][3] + b1;
            if (BNSTAT) {
                ps0[ni] += v00 + v10;  q0s[ni] += v00 * v00 + v10 * v10;
                ps1[ni] += v01 + v11;  q1s[ni] += v01 * v01 + v11 * v11;
            }
            if (F16OUT) {
                size_t o0 = (size_t)z * cS + (size_t)row * Ntot + col;
                size_t o1 = (size_t)z * cS + (size_t)(row + 8) * Ntot + col;
                *(uint32_t*)(Cp + o0) = pack_h2(v00, v01);
                *(uint32_t*)(Cp + o1) = pack_h2(v10, v11);
            } else {
                float* C = Cf + (size_t)z * cS;
                float2 w0 = { v00, v01 };
                float2 w1 = { v10, v11 };
                *(float2*)(C + (size_t)row * Ntot + col) = w0;
                *(float2*)(C + (size_t)(row + 8) * Ntot + col) = w1;
            }
        }
    }

    if (BNSTAT) {
        __syncthreads();
        for (int t = tid; t < NT; t += 256) { bn_s[t] = 0.f; bn_s2[t] = 0.f; }
        __syncthreads();
#pragma unroll
        for (int ni = 0; ni < NF; ++ni) {
            float a = ps0[ni], b = ps1[ni], c = q0s[ni], d = q1s[ni];
#pragma unroll
            for (int o = 4; o <= 16; o <<= 1) {
                a += __shfl_xor_sync(0xffffffffu, a, o);
                b += __shfl_xor_sync(0xffffffffu, b, o);
                c += __shfl_xor_sync(0xffffffffu, c, o);
                d += __shfl_xor_sync(0xffffffffu, d, o);
            }
            if (lane < 4) {
                int cl = wn * WN + ni * 8 + lc;
                atomicAdd(&bn_s[cl], a);  atomicAdd(&bn_s[cl + 1], b);
                atomicAdd(&bn_s2[cl], c); atomicAdd(&bn_s2[cl + 1], d);
            }
        }
        __syncthreads();
        for (int t = tid; t < NT; t += 256) {
            atomicAdd(&gsum[n0 + t], bn_s[t]);
            atomicAdd(&gsum2[n0 + t], bn_s2[t]);
        }
    }
}

// ---------------- prep kernels ----------------
__global__ void zero_all_kernel(float* cs, float* sA, float* s2A, float* sB, float* s2B)
{
    int i = blockIdx.x * 1024 + threadIdx.x;
    if (i < BB * MCB) cs[i] = 0.f;
    if (i < CIN) { sA[i] = 0.f; s2A[i] = 0.f; sB[i] = 0.f; s2B[i] = 0.f; }
}

__global__ void prep_cvt_kernel(const float* __restrict__ w1, const float* __restrict__ w2,
                                const float* __restrict__ w3, const float* __restrict__ cen,
                                f16* __restrict__ w1o, f16* __restrict__ w2o,
                                f16* __restrict__ w3o, f16* __restrict__ cto)
{
    const int W = COUT * CIN;
    const int CT = COUT * MCB;
    int i = blockIdx.x * 256 + threadIdx.x;
    if (i < W) {
        w1o[i] = __float2half_rn(w1[i]);
    } else if (i < 2 * W) {
        int j = i - W;
        w2o[j] = __float2half_rn(w2[j]);
    } else if (i < 3 * W) {
        int j = i - 2 * W;
        w3o[j] = __float2half_rn(w3[j]);
    } else if (i < 3 * W + CT) {
        int j = i - 3 * W;
        int c = j / MCB, k = j % MCB;
        cto[k * COUT + c] = __float2half_rn(cen[j]);
    }
}

__global__ void transpose_in_f16(const float* __restrict__ in, f16* __restrict__ o)
{
    __shared__ float t[32][33];
    const int b = blockIdx.z;
    const int n0 = blockIdx.x * 32, c0 = blockIdx.y * 32;
    const float* ip = in + (size_t)b * CIN * HW;
#pragma unroll
    for (int i = 0; i < 32; i += 8)
        t[threadIdx.y + i][threadIdx.x] = ip[(size_t)(c0 + threadIdx.y + i) * HW + n0 + threadIdx.x];
    __syncthreads();
#pragma unroll
    for (int i = 0; i < 32; i += 8) {
        float v = t[threadIdx.x][threadIdx.y + i];
        size_t oo = (size_t)b * HW * CIN + (size_t)(n0 + threadIdx.y + i) * CIN + c0 + threadIdx.x;
        o[oo] = __float2half_rn(v);
    }
}

__global__ void scale_centers_f16(const float* __restrict__ centers, const float* __restrict__ colsum,
                                  f16* __restrict__ o)
{
    int i = blockIdx.x * 256 + threadIdx.x;
    int b = blockIdx.y;
    if (i < COUT * MCB) {
        int k = i % MCB;
        float r = 1.f / (1e-6f + colsum[b * MCB + k]);
        o[(size_t)b * COUT * MCB + i] = __float2half_rn(centers[i] * r);
    }
}

// ---------------- softmax: single pass, fp16 out + colsum ----------------
__global__ void softmax_colsum_f16(const float* __restrict__ att, float* __restrict__ colsum,
                                   f16* __restrict__ o)
{
    const int warp = threadIdx.x >> 5;
    const int lane = threadIdx.x & 31;
    const int b = blockIdx.y;
    const int rowBase = blockIdx.x * 256 + warp * 32;
    float cacc[6] = {0.f, 0.f, 0.f, 0.f, 0.f, 0.f};

    for (int r = 0; r < 32; ++r) {
        const int n = rowBase + r;
        const size_t base = ((size_t)b * HW + n) * MCB;
        const float* p = att + base;
        float v[6];
        float mx = -1e30f;
#pragma unroll
        for (int j = 0; j < 6; ++j) { v[j] = p[j * 32 + lane]; mx = fmaxf(mx, v[j]); }
#pragma unroll
        for (int o2 = 16; o2 > 0; o2 >>= 1) mx = fmaxf(mx, __shfl_xor_sync(0xffffffffu, mx, o2));
        float s = 0.f;
#pragma unroll
        for (int j = 0; j < 6; ++j) { v[j] = expf(v[j] - mx); s += v[j]; }
#pragma unroll
        for (int o2 = 16; o2 > 0; o2 >>= 1) s += __shfl_xor_sync(0xffffffffu, s, o2);
        const float inv = 1.f / s;
#pragma unroll
        for (int j = 0; j < 6; ++j) {
            float ov = v[j] * inv;
            cacc[j] += ov;
            o[base + j * 32 + lane] = __float2half_rn(ov);
        }
    }
#pragma unroll
    for (int j = 0; j < 6; ++j)
        atomicAdd(&colsum[b * MCB + j * 32 + lane], cacc[j]);
}

// ---------------- BN apply (inline finalize) ----------------
__global__ void bn_apply_res_f16(const float* __restrict__ t,
                                 const f16* __restrict__ x16,
                                 const float* __restrict__ gsum, const float* __restrict__ gsum2,
                                 const float* __restrict__ gamma, const float* __restrict__ beta,
                                 f16* __restrict__ o)
{
    size_t i = (size_t)blockIdx.x * blockDim.x + threadIdx.x;
    const int c4 = (int)(i & 127);
    const float N = (float)((size_t)BB * HW);
    const float4 sm = ((const float4*)gsum)[c4];
    const float4 s2 = ((const float4*)gsum2)[c4];
    const float4 gm = ((const float4*)gamma)[c4];
    const float4 bt = ((const float4*)beta)[c4];
    float4 sc, sh;
    {
        float m, vr;
        m = sm.x / N; vr = s2.x / N - m * m; sc.x = gm.x * rsqrtf(vr + EPS_BN); sh.x = bt.x - m * sc.x;
        m = sm.y / N; vr = s2.y / N - m * m; sc.y = gm.y * rsqrtf(vr + EPS_BN); sh.y = bt.y - m * sc.y;
        m = sm.z / N; vr = s2.z / N - m * m; sc.z = gm.z * rsqrtf(vr + EPS_BN); sh.z = bt.z - m * sc.z;
        m = sm.w / N; vr = s2.w / N - m * m; sc.w = gm.w * rsqrtf(vr + EPS_BN); sh.w = bt.w - m * sc.w;
    }
    float4 v = ((const float4*)t)[i];
    uint2 xu = *(const uint2*)(x16 + i * 4);
    __half2 x0 = *(__half2*)&xu.x;
    __half2 x1 = *(__half2*)&xu.y;
    float r0, r1, r2, r3;
    r0 = fmaxf(fmaf(sc.x, v.x, sh.x), 0.f) + __half2float(x0.x);
    r1 = fmaxf(fmaf(sc.y, v.y, sh.y), 0.f) + __half2float(x0.y);
    r2 = fmaxf(fmaf(sc.z, v.z, sh.z), 0.f) + __half2float(x1.x);
    r3 = fmaxf(fmaf(sc.w, v.w, sh.w), 0.f) + __half2float(x1.y);
    uint2 ou = { pack_h2(r0, r1), pack_h2(r2, r3) };
    *(uint2*)(o + i * 4) = ou;
}

__global__ void bn_apply_transpose_kernel(const float* __restrict__ in,
                                          const float* __restrict__ gsum, const float* __restrict__ gsum2,
                                          const float* __restrict__ gamma, const float* __restrict__ beta,
                                          float* __restrict__ out)
{
    __shared__ float t[32][33];
    const int b = blockIdx.z;
    const int n0 = blockIdx.x * 32, c0 = blockIdx.y * 32;
    const float* ip = in + (size_t)b * HW * CIN;
    float* op = out + (size_t)b * CIN * HW;
    const int c = c0 + threadIdx.x;
    const float N = (float)((size_t)BB * HW);
    const float mean = gsum[c] / N;
    const float var = gsum2[c] / N - mean * mean;
    const float sc = gamma[c] * rsqrtf(var + EPS_BN);
    const float sh = beta[c] - mean * sc;
#pragma unroll
    for (int i = 0; i < 32; i += 8) {
        float v = ip[(size_t)(n0 + threadIdx.y + i) * CIN + c];
        t[threadIdx.y + i][threadIdx.x] = fmaxf(fmaf(sc, v, sh), 0.f);
    }
    __syncthreads();
#pragma unroll
    for (int i = 0; i < 32; i += 8)
        op[(size_t)(c0 + threadIdx.y + i) * HW + n0 + threadIdx.x] = t[threadIdx.x][threadIdx.y + i];
}

// ---------------- host-side tensor map helper ----------------
typedef CUresult (*EncFn)(CUtensorMap*, CUtensorMapDataType, cuuint32_t, void*,
                          const cuuint64_t*, const cuuint64_t*, const cuuint32_t*, const cuuint32_t*,
                          CUtensorMapInterleave, CUtensorMapSwizzle, CUtensorMapL2promotion,
                          CUtensorMapFloatOOBfill);

static void make_map(EncFn enc, CUtensorMap* m, void* base, uint64_t kd, uint64_t rows, uint32_t box_rows)
{
    cuuint64_t dims[2] = { kd, rows };
    cuuint64_t strides[1] = { kd * 2 };
    cuuint32_t box[2] = { 32, box_rows };
    cuuint32_t es[2] = { 1, 1 };
    enc(m, CU_TENSOR_MAP_DATA_TYPE_FLOAT16, 2, base, dims, strides, box, es,
        CU_TENSOR_MAP_INTERLEAVE_NONE, CU_TENSOR_MAP_SWIZZLE_64B,
        CU_TENSOR_MAP_L2_PROMOTION_L2_128B, CU_TENSOR_MAP_FLOAT_OOB_FILL_NONE);
}

// ---------------- launch ----------------
extern "C" void kernel_launch(void* const* d_in, const int* in_sizes, int n_in,
                              void* d_out, int out_size)
{
    const float* x       = (const float*)d_in[0];
    const float* centers = (const float*)d_in[1];
    const float* conv1_w = (const float*)d_in[2];
    const float* conv1_b = (const float*)d_in[3];
    const float* conv2_w = (const float*)d_in[4];
    const float* bn2_g   = (const float*)d_in[5];
    const float* bn2_b   = (const float*)d_in[6];
    const float* conv3_w = (const float*)d_in[7];
    const float* conv3_b = (const float*)d_in[8];
    const float* bn3_g   = (const float*)d_in[9];
    const float* bn3_b   = (const float*)d_in[10];
    float* out = (float*)d_out;

    f16 *xT, *b1, *b2, *att16, *ct, *cs, *w1, *w2, *w3;
    float *buf1, *att, *colsum, *sumA, *sum2A, *sumB, *sum2B;
    cudaGetSymbolAddress((void**)&xT, g_xT);
    cudaGetSymbolAddress((void**)&b1, g_b1);
    cudaGetSymbolAddress((void**)&b2, g_b2);
    cudaGetSymbolAddress((void**)&att16, g_att16);
    cudaGetSymbolAddress((void**)&ct, g_ct);
    cudaGetSymbolAddress((void**)&cs, g_cs);
    cudaGetSymbolAddress((void**)&w1, g_w1);
    cudaGetSymbolAddress((void**)&w2, g_w2);
    cudaGetSymbolAddress((void**)&w3, g_w3);
    cudaGetSymbolAddress((void**)&buf1, g_buf1);
    cudaGetSymbolAddress((void**)&att, g_att);
    cudaGetSymbolAddress((void**)&colsum, g_colsum);
    cudaGetSymbolAddress((void**)&sumA, g_sumA);
    cudaGetSymbolAddress((void**)&sum2A, g_sum2A);
    cudaGetSymbolAddress((void**)&sumB, g_sumB);
    cudaGetSymbolAddress((void**)&sum2B, g_sum2B);

    void* pfn = nullptr;
    cudaDriverEntryPointQueryResult qr;
    cudaGetDriverEntryPoint("cuTensorMapEncodeTiled", &pfn, cudaEnableDefault, &qr);
    EncFn enc = (EncFn)pfn;

    const uint64_t RA = (uint64_t)BB * HW;
    CUtensorMap tX, tB1, tB2, tAtt, tW1, tW2, tW3, tCt, tCs;
    make_map(enc, &tX,   xT,   CIN, RA, 128);
    make_map(enc, &tB1,  b1,   COUT, RA, 128);
    make_map(enc, &tB2,  b2,   COUT, RA, 128);
    make_map(enc, &tAtt, att16, MCB, RA, 128);
    make_map(enc, &tW1,  w1,   CIN, COUT, 128);
    make_map(enc, &tW2,  w2,   COUT, CIN, 128);
    make_map(enc, &tW3,  w3,   CIN, CIN, 128);
    make_map(enc, &tCt,  ct,   COUT, MCB, 96);
    make_map(enc, &tCs,  cs,   MCB, (uint64_t)BB * COUT, 128);

    const size_t S  = (size_t)HW * CIN;
    const size_t SA = (size_t)HW * MCB;

    const int SM128 = 3 * (8192 + 128 * 64);   // 49152
    const int SM96  = 3 * (8192 + 96 * 64);    // 43008
    cudaFuncSetAttribute(gemm_tma<128, true,  true,  false>, cudaFuncAttributeMaxDynamicSharedMemorySize, SM128);
    cudaFuncSetAttribute(gemm_tma<96,  false, false, false>, cudaFuncAttributeMaxDynamicSharedMemorySize, SM96);
    cudaFuncSetAttribute(gemm_tma<128, false, true,  false>, cudaFuncAttributeMaxDynamicSharedMemorySize, SM128);
    cudaFuncSetAttribute(gemm_tma<128, false, false, true >, cudaFuncAttributeMaxDynamicSharedMemorySize, SM128);
    cudaFuncSetAttribute(gemm_tma<128, true,  false, true >, cudaFuncAttributeMaxDynamicSharedMemorySize, SM128);

    // 0. prep
    zero_all_kernel<<<3, 1024>>>(colsum, sumA, sum2A, sumB, sum2B);
    transpose_in_f16<<<dim3(HW / 32, CIN / 32, BB), dim3(32, 8)>>>(x, xT);
    prep_cvt_kernel<<<(3 * COUT * CIN + COUT * MCB + 255) / 256, 256>>>(
        conv1_w, conv2_w, conv3_w, centers, w1, w2, w3, ct);

    // 1. conv1 -> fp16 b1
    gemm_tma<128, true, true, false><<<dim3(4, 32, BB), 256, SM128>>>(
        tX, tW1, conv1_b, nullptr, b1, nullptr, nullptr, CIN, COUT, 0, S);

    // 2. att raw -> fp32 att
    gemm_tma<96, false, false, false><<<dim3(2, 32, BB), 256, SM96>>>(
        tB1, tCt, nullptr, att, nullptr, nullptr, nullptr, COUT, MCB, 0, SA);

    // 3. softmax (single pass, fp16 out) + batch-scaled centers
    softmax_colsum_f16<<<dim3(HW / 256, BB), 256>>>(att, colsum, att16);
    scale_centers_f16<<<dim3((COUT * MCB + 255) / 256, BB), 256>>>(centers, colsum, cs);

    // 4. recon = att_sm @ (scaled centers)^T -> fp16 b2
    gemm_tma<128, false, true, false><<<dim3(4, 32, BB), 256, SM128>>>(
        tAtt, tCs, nullptr, nullptr, b2, nullptr, nullptr, MCB, COUT, COUT, S);

    // 5. conv2 -> fp32 buf1 (+fused BN stats -> sumA)
    gemm_tma<128, false, false, true><<<dim3(4, 32, BB), 256, SM128>>>(
        tB2, tW2, nullptr, buf1, nullptr, sumA, sum2A, COUT, CIN, 0, S);

    // 6. BN2 apply (inline finalize) + ReLU + residual -> fp16 b2
    bn_apply_res_f16<<<(unsigned)(((size_t)BB * S / 4) / 256), 256>>>(
        buf1, xT, sumA, sum2A, bn2_g, bn2_b, b2);

    // 7. conv3 -> fp32 buf1 (+fused BN stats -> sumB)
    gemm_tma<128, true, false, true><<<dim3(4, 32, BB), 256, SM128>>>(
        tB2, tW3, conv3_b, buf1, nullptr, sumB, sum2B, CIN, CIN, 0, S);

    // 8. BN3 apply (inline finalize) + ReLU + transpose -> out
    bn_apply_transpose_kernel<<<dim3(HW / 32, CIN / 32, BB), dim3(32, 8)>>>(
        buf1, sumB, sum2B, bn3_g, bn3_b, out);
}

// round 17
// speedup vs baseline: 2.0218x; 1.0733x over previous
#include <cuda.h>
#include <cuda_runtime.h>
#include <cuda_bf16.h>
#include <cuda_fp16.h>
#include <math.h>
#include <stdint.h>

// ---------------- problem constants ----------------
#define BB   16
#define CIN  512
#define COUT 512
#define HW   4096
#define MCB  192
#define EPS_BN 1e-5f
#define BK   64          // K elements per pipeline stage (two 32-wide sub-tiles)

typedef __half f16;

#define SWZ(o) ((o) ^ (((o) >> 3) & 0x30))

// ---------------- scratch (device globals) ----------------
__device__ f16   g_xT  [(size_t)BB * HW * CIN];
__device__ f16   g_b1  [(size_t)BB * HW * COUT];   // also conv2/conv3 output buffer
__device__ f16   g_b2  [(size_t)BB * HW * CIN];
__device__ f16   g_att16[(size_t)BB * HW * MCB];
__device__ float g_att  [(size_t)BB * HW * MCB];
__device__ f16   g_ct  [MCB * COUT];
__device__ f16   g_cs  [(size_t)BB * COUT * MCB];
__device__ f16   g_w1  [COUT * CIN];
__device__ f16   g_w2  [CIN * COUT];
__device__ f16   g_w3  [CIN * CIN];
__device__ float g_colsum[BB * MCB];
__device__ float g_sumA [CIN];
__device__ float g_sum2A[CIN];
__device__ float g_sumB [CIN];
__device__ float g_sum2B[CIN];

// ---------------- device helpers ----------------
__device__ __forceinline__ uint32_t smem_u32(const void* p) {
    uint32_t a;
    asm("{ .reg .u64 t; cvta.to.shared.u64 t, %1; cvt.u32.u64 %0, t; }" : "=r"(a) : "l"(p));
    return a;
}
__device__ __forceinline__ void ldmatrix_x4(uint32_t& r0, uint32_t& r1, uint32_t& r2, uint32_t& r3, uint32_t addr) {
    asm volatile("ldmatrix.sync.aligned.m8n8.x4.shared.b16 {%0,%1,%2,%3}, [%4];"
                 : "=r"(r0), "=r"(r1), "=r"(r2), "=r"(r3) : "r"(addr));
}
__device__ __forceinline__ void ldmatrix_x2(uint32_t& r0, uint32_t& r1, uint32_t addr) {
    asm volatile("ldmatrix.sync.aligned.m8n8.x2.shared.b16 {%0,%1}, [%2];"
                 : "=r"(r0), "=r"(r1) : "r"(addr));
}
__device__ __forceinline__ void mma_f16(float* c, uint32_t a0, uint32_t a1, uint32_t a2, uint32_t a3,
                                        uint32_t b0, uint32_t b1) {
    asm("mma.sync.aligned.m16n8k16.row.col.f32.f16.f16.f32 "
        "{%0,%1,%2,%3}, {%4,%5,%6,%7}, {%8,%9}, {%0,%1,%2,%3};"
        : "+f"(c[0]), "+f"(c[1]), "+f"(c[2]), "+f"(c[3])
        : "r"(a0), "r"(a1), "r"(a2), "r"(a3), "r"(b0), "r"(b1));
}
__device__ __forceinline__ uint32_t pack_h2(float x, float y) {
    __half2 h = __floats2half2_rn(x, y);
    return *(uint32_t*)&h;
}

#define MBARRIER_INIT(addr, cnt) \
    asm volatile("mbarrier.init.shared.b64 [%0], %1;" :: "r"((uint32_t)(addr)), "r"((uint32_t)(cnt)) : "memory")
#define MBARRIER_EXPECT_TX(addr, tx) \
    asm volatile("mbarrier.arrive.expect_tx.shared.b64 _, [%0], %1;" :: "r"((uint32_t)(addr)), "r"((uint32_t)(tx)) : "memory")
#define MBARRIER_ARRIVE(addr) \
    asm volatile("mbarrier.arrive.shared.b64 _, [%0];" :: "r"((uint32_t)(addr)) : "memory")
#define MBARRIER_WAIT_PARITY(addr, par) do { \
    uint32_t _m = (uint32_t)(addr); uint32_t _p = (uint32_t)(par); uint32_t _d; \
    asm volatile("{\n\t.reg .pred p;\n\tmbarrier.try_wait.parity.acquire.cta.shared::cta.b64 p, [%1], %2;\n\tselp.b32 %0, 1, 0, p;\n\t}" \
        : "=r"(_d) : "r"(_m), "r"(_p) : "memory"); \
    if (!_d) { \
        asm volatile("{\n\t.reg .pred P1;\n\tWL_%=:\n\tmbarrier.try_wait.parity.acquire.cta.shared::cta.b64 P1, [%0], %1, 0x989680;\n\t@P1 bra.uni WD_%=;\n\tbra.uni WL_%=;\n\tWD_%=:\n\t}" \
            :: "r"(_m), "r"(_p) : "memory"); \
    } } while (0)
#define TMA2D(dst, map, cx, cy, bar) \
    asm volatile("cp.async.bulk.tensor.2d.shared::cta.global.tile.mbarrier::complete_tx::bytes " \
                 "[%0], [%1, {%2, %3}], [%4];" \
        :: "r"((uint32_t)(dst)), "l"(map), "r"((int)(cx)), "r"((int)(cy)), "r"((uint32_t)(bar)) : "memory")

// ---------------- one-term fp16 GEMM, 3-stage TMA pipeline, BK=64 ----------------
// C[m,n] = sum_k A[m,k]*B[n,k] (+bias[n]), fp32 accumulate.
// Stage layout: A sub0 [128x64B] @0, A sub1 @8192, B sub0 @16384, B sub1 @16384+NT*64.
template<int NT, bool BIAS, bool F16OUT, bool BNSTAT>
__global__ __launch_bounds__(256, 2)
void gemm_tma(const __grid_constant__ CUtensorMap mA,
              const __grid_constant__ CUtensorMap mB,
              const float* __restrict__ bias,
              float* __restrict__ Cf, f16* __restrict__ Cp,
              float* __restrict__ gsum, float* __restrict__ gsum2,
              int Kd, int Ntot, int bZmul, size_t cS)
{
    constexpr int WN = NT / 4;
    constexpr int NF = WN / 8;
    constexpr int OFF_B = 16384;
    constexpr int BSUB  = NT * 64;
    constexpr int STAGE = 16384 + 2 * BSUB;   // 32768 (NT=128) / 28672 (NT=96)

    extern __shared__ __align__(1024) char dsm[];
    __shared__ __align__(8) uint64_t mbar_full[3];
    __shared__ __align__(8) uint64_t mbar_empty[3];
    __shared__ float bn_s[NT];
    __shared__ float bn_s2[NT];

    const uint32_t sbase = smem_u32(dsm);
    const int tid = threadIdx.x;
    const int lane = tid & 31;
    const int wid = tid >> 5;
    const int wm = wid & 1;
    const int wn = wid >> 1;
    const int m0 = blockIdx.y * 128;
    const int n0 = blockIdx.x * NT;
    const int z  = blockIdx.z;

    const int NC = Kd / BK;
    const int cyA = z * HW + m0;
    const int cyB = z * bZmul + n0;

    if (tid == 0) {
#pragma unroll
        for (int s = 0; s < 3; ++s) {
            MBARRIER_INIT(smem_u32(&mbar_full[s]), 1);
            MBARRIER_INIT(smem_u32(&mbar_empty[s]), 8);
        }
    }
    __syncthreads();

    auto issue = [&](int i) {
        const int s = i % 3;
        const uint32_t bar = smem_u32(&mbar_full[s]);
        const uint32_t st = sbase + s * STAGE;
        MBARRIER_EXPECT_TX(bar, (uint32_t)STAGE);
        const int cx = i * BK;
        TMA2D(st,                 &mA, cx,      cyA, bar);
        TMA2D(st + 8192,          &mA, cx + 32, cyA, bar);
        TMA2D(st + OFF_B,         &mB, cx,      cyB, bar);
        TMA2D(st + OFF_B + BSUB,  &mB, cx + 32, cyB, bar);
    };
    if (tid == 0) { issue(0); issue(1); issue(2); }

    float acc[4][NF][4];
#pragma unroll
    for (int mi = 0; mi < 4; ++mi)
#pragma unroll
        for (int ni = 0; ni < NF; ++ni)
#pragma unroll
            for (int j = 0; j < 4; ++j) acc[mi][ni][j] = 0.f;

    const int arow = wm * 64;
    const int brow = wn * WN;
    const int l7 = lane & 7;
    const int aq = lane >> 3;
    const int arsel = (aq & 1) * 8;
    const int acsel = (aq >> 1) * 16;
    const int b4r = ((lane >> 4) & 1) * 8;
    const int b4c = ((lane >> 3) & 1) * 16;
    const int b2c = ((lane >> 3) & 1) * 16;

    for (int i = 0; i < NC; ++i) {
        const int s = i % 3;
        const int par = (i / 3) & 1;
        MBARRIER_WAIT_PARITY(smem_u32(&mbar_full[s]), par);

        const uint32_t st = sbase + s * STAGE;

#pragma unroll
        for (int k16 = 0; k16 < 4; ++k16) {
            const int sub = k16 >> 1;
            const int kb = (k16 & 1) * 32;
            const uint32_t sA = st + sub * 8192;
            const uint32_t sB = st + OFF_B + sub * BSUB;

            uint32_t bh[NF][2];
#pragma unroll
            for (int p = 0; p < NF / 2; ++p) {
                uint32_t bo = SWZ((uint32_t)((brow + p * 16 + b4r + l7) * 64 + kb + b4c));
                ldmatrix_x4(bh[2*p][0], bh[2*p][1], bh[2*p+1][0], bh[2*p+1][1], sB + bo);
            }
            if (NF & 1) {
                const int ni = NF - 1;
                uint32_t bo = SWZ((uint32_t)((brow + ni * 8 + l7) * 64 + kb + b2c));
                ldmatrix_x2(bh[ni][0], bh[ni][1], sB + bo);
            }
#pragma unroll
            for (int mi = 0; mi < 4; ++mi) {
                uint32_t ao = SWZ((uint32_t)((arow + mi * 16 + arsel + l7) * 64 + kb + acsel));
                uint32_t a0, a1, a2, a3;
                ldmatrix_x4(a0, a1, a2, a3, sA + ao);
#pragma unroll
                for (int ni = 0; ni < NF; ++ni)
                    mma_f16(acc[mi][ni], a0, a1, a2, a3, bh[ni][0], bh[ni][1]);
            }
        }

        if (lane == 0) MBARRIER_ARRIVE(smem_u32(&mbar_empty[s]));
        if (tid == 0 && i + 3 < NC) {
            MBARRIER_WAIT_PARITY(smem_u32(&mbar_empty[s]), par);
            issue(i + 3);
        }
    }

    // ---- epilogue ----
    const int l4 = lane >> 2;
    const int lc = (lane & 3) * 2;
    float ps0[NF], ps1[NF], q0s[NF], q1s[NF];
#pragma unroll
    for (int ni = 0; ni < NF; ++ni) { ps0[ni] = ps1[ni] = q0s[ni] = q1s[ni] = 0.f; }

#pragma unroll
    for (int mi = 0; mi < 4; ++mi) {
        const int row = m0 + wm * 64 + mi * 16 + l4;
#pragma unroll
        for (int ni = 0; ni < NF; ++ni) {
            const int col = n0 + wn * WN + ni * 8 + lc;
            float b0 = BIAS ? bias[col] : 0.f;
            float b1 = BIAS ? bias[col + 1] : 0.f;
            float v00 = acc[mi][ni][0] + b0, v01 = acc[mi][ni][1] + b1;
            float v10 = acc[mi][ni][2] + b0, v11 = acc[mi][ni][3] + b1;
            if (BNSTAT) {
                ps0[ni] += v00 + v10;  q0s[ni] += v00 * v00 + v10 * v10;
                ps1[ni] += v01 + v11;  q1s[ni] += v01 * v01 + v11 * v11;
            }
            if (F16OUT) {
                size_t o0 = (size_t)z * cS + (size_t)row * Ntot + col;
                size_t o1 = (size_t)z * cS + (size_t)(row + 8) * Ntot + col;
                *(uint32_t*)(Cp + o0) = pack_h2(v00, v01);
                *(uint32_t*)(Cp + o1) = pack_h2(v10, v11);
            } else {
                float* C = Cf + (size_t)z * cS;
                float2 w0 = { v00, v01 };
                float2 w1 = { v10, v11 };
                *(float2*)(C + (size_t)row * Ntot + col) = w0;
                *(float2*)(C + (size_t)(row + 8) * Ntot + col) = w1;
            }
        }
    }

    if (BNSTAT) {
        __syncthreads();
        for (int t = tid; t < NT; t += 256) { bn_s[t] = 0.f; bn_s2[t] = 0.f; }
        __syncthreads();
#pragma unroll
        for (int ni = 0; ni < NF; ++ni) {
            float a = ps0[ni], b = ps1[ni], c = q0s[ni], d = q1s[ni];
#pragma unroll
            for (int o = 4; o <= 16; o <<= 1) {
                a += __shfl_xor_sync(0xffffffffu, a, o);
                b += __shfl_xor_sync(0xffffffffu, b, o);
                c += __shfl_xor_sync(0xffffffffu, c, o);
                d += __shfl_xor_sync(0xffffffffu, d, o);
            }
            if (lane < 4) {
                int cl = wn * WN + ni * 8 + lc;
                atomicAdd(&bn_s[cl], a);  atomicAdd(&bn_s[cl + 1], b);
                atomicAdd(&bn_s2[cl], c); atomicAdd(&bn_s2[cl + 1], d);
            }
        }
        __syncthreads();
        for (int t = tid; t < NT; t += 256) {
            atomicAdd(&gsum[n0 + t], bn_s[t]);
            atomicAdd(&gsum2[n0 + t], bn_s2[t]);
        }
    }
}

// ---------------- prep kernels ----------------
__global__ void zero_all_kernel(float* cs, float* sA, float* s2A, float* sB, float* s2B)
{
    int i = blockIdx.x * 1024 + threadIdx.x;
    if (i < BB * MCB) cs[i] = 0.f;
    if (i < CIN) { sA[i] = 0.f; s2A[i] = 0.f; sB[i] = 0.f; s2B[i] = 0.f; }
}

__global__ void prep_cvt_kernel(const float* __restrict__ w1, const float* __restrict__ w2,
                                const float* __restrict__ w3, const float* __restrict__ cen,
                                f16* __restrict__ w1o, f16* __restrict__ w2o,
                                f16* __restrict__ w3o, f16* __restrict__ cto)
{
    const int W = COUT * CIN;
    const int CT = COUT * MCB;
    int i = blockIdx.x * 256 + threadIdx.x;
    if (i < W) {
        w1o[i] = __float2half_rn(w1[i]);
    } else if (i < 2 * W) {
        int j = i - W;
        w2o[j] = __float2half_rn(w2[j]);
    } else if (i < 3 * W) {
        int j = i - 2 * W;
        w3o[j] = __float2half_rn(w3[j]);
    } else if (i < 3 * W + CT) {
        int j = i - 3 * W;
        int c = j / MCB, k = j % MCB;
        cto[k * COUT + c] = __float2half_rn(cen[j]);
    }
}

__global__ void transpose_in_f16(const float* __restrict__ in, f16* __restrict__ o)
{
    __shared__ float t[32][33];
    const int b = blockIdx.z;
    const int n0 = blockIdx.x * 32, c0 = blockIdx.y * 32;
    const float* ip = in + (size_t)b * CIN * HW;
#pragma unroll
    for (int i = 0; i < 32; i += 8)
        t[threadIdx.y + i][threadIdx.x] = ip[(size_t)(c0 + threadIdx.y + i) * HW + n0 + threadIdx.x];
    __syncthreads();
#pragma unroll
    for (int i = 0; i < 32; i += 8) {
        float v = t[threadIdx.x][threadIdx.y + i];
        size_t oo = (size_t)b * HW * CIN + (size_t)(n0 + threadIdx.y + i) * CIN + c0 + threadIdx.x;
        o[oo] = __float2half_rn(v);
    }
}

__global__ void scale_centers_f16(const float* __restrict__ centers, const float* __restrict__ colsum,
                                  f16* __restrict__ o)
{
    int i = blockIdx.x * 256 + threadIdx.x;
    int b = blockIdx.y;
    if (i < COUT * MCB) {
        int k = i % MCB;
        float r = 1.f / (1e-6f + colsum[b * MCB + k]);
        o[(size_t)b * COUT * MCB + i] = __float2half_rn(centers[i] * r);
    }
}

// ---------------- softmax: single pass, fp16 out + colsum ----------------
__global__ void softmax_colsum_f16(const float* __restrict__ att, float* __restrict__ colsum,
                                   f16* __restrict__ o)
{
    const int warp = threadIdx.x >> 5;
    const int lane = threadIdx.x & 31;
    const int b = blockIdx.y;
    const int rowBase = blockIdx.x * 256 + warp * 32;
    float cacc[6] = {0.f, 0.f, 0.f, 0.f, 0.f, 0.f};

    for (int r = 0; r < 32; ++r) {
        const int n = rowBase + r;
        const size_t base = ((size_t)b * HW + n) * MCB;
        const float* p = att + base;
        float v[6];
        float mx = -1e30f;
#pragma unroll
        for (int j = 0; j < 6; ++j) { v[j] = p[j * 32 + lane]; mx = fmaxf(mx, v[j]); }
#pragma unroll
        for (int o2 = 16; o2 > 0; o2 >>= 1) mx = fmaxf(mx, __shfl_xor_sync(0xffffffffu, mx, o2));
        float s = 0.f;
#pragma unroll
        for (int j = 0; j < 6; ++j) { v[j] = expf(v[j] - mx); s += v[j]; }
#pragma unroll
        for (int o2 = 16; o2 > 0; o2 >>= 1) s += __shfl_xor_sync(0xffffffffu, s, o2);
        const float inv = 1.f / s;
#pragma unroll
        for (int j = 0; j < 6; ++j) {
            float ov = v[j] * inv;
            cacc[j] += ov;
            o[base + j * 32 + lane] = __float2half_rn(ov);
        }
    }
#pragma unroll
    for (int j = 0; j < 6; ++j)
        atomicAdd(&colsum[b * MCB + j * 32 + lane], cacc[j]);
}

// ---------------- BN apply (inline finalize), fp16 input ----------------
__global__ void bn_apply_res_f16(const f16* __restrict__ t,
                                 const f16* __restrict__ x16,
                                 const float* __restrict__ gsum, const float* __restrict__ gsum2,
                                 const float* __restrict__ gamma, const float* __restrict__ beta,
                                 f16* __restrict__ o)
{
    size_t i = (size_t)blockIdx.x * blockDim.x + threadIdx.x;   // 4-elem index
    const int c4 = (int)(i & 127);
    const float N = (float)((size_t)BB * HW);
    const float4 sm = ((const float4*)gsum)[c4];
    const float4 s2 = ((const float4*)gsum2)[c4];
    const float4 gm = ((const float4*)gamma)[c4];
    const float4 bt = ((const float4*)beta)[c4];
    float4 sc, sh;
    {
        float m, vr;
        m = sm.x / N; vr = s2.x / N - m * m; sc.x = gm.x * rsqrtf(vr + EPS_BN); sh.x = bt.x - m * sc.x;
        m = sm.y / N; vr = s2.y / N - m * m; sc.y = gm.y * rsqrtf(vr + EPS_BN); sh.y = bt.y - m * sc.y;
        m = sm.z / N; vr = s2.z / N - m * m; sc.z = gm.z * rsqrtf(vr + EPS_BN); sh.z = bt.z - m * sc.z;
        m = sm.w / N; vr = s2.w / N - m * m; sc.w = gm.w * rsqrtf(vr + EPS_BN); sh.w = bt.w - m * sc.w;
    }
    uint2 tu = *(const uint2*)(t + i * 4);
    __half2 t0 = *(__half2*)&tu.x;
    __half2 t1 = *(__half2*)&tu.y;
    uint2 xu = *(const uint2*)(x16 + i * 4);
    __half2 x0 = *(__half2*)&xu.x;
    __half2 x1 = *(__half2*)&xu.y;
    float r0, r1, r2, r3;
    r0 = fmaxf(fmaf(sc.x, __half2float(t0.x), sh.x), 0.f) + __half2float(x0.x);
    r1 = fmaxf(fmaf(sc.y, __half2float(t0.y), sh.y), 0.f) + __half2float(x0.y);
    r2 = fmaxf(fmaf(sc.z, __half2float(t1.x), sh.z), 0.f) + __half2float(x1.x);
    r3 = fmaxf(fmaf(sc.w, __half2float(t1.y), sh.w), 0.f) + __half2float(x1.y);
    uint2 ou = { pack_h2(r0, r1), pack_h2(r2, r3) };
    *(uint2*)(o + i * 4) = ou;
}

__global__ void bn_apply_transpose_kernel(const f16* __restrict__ in,
                                          const float* __restrict__ gsum, const float* __restrict__ gsum2,
                                          const float* __restrict__ gamma, const float* __restrict__ beta,
                                          float* __restrict__ out)
{
    __shared__ float t[32][33];
    const int b = blockIdx.z;
    const int n0 = blockIdx.x * 32, c0 = blockIdx.y * 32;
    const f16* ip = in + (size_t)b * HW * CIN;
    float* op = out + (size_t)b * CIN * HW;
    const int c = c0 + threadIdx.x;
    const float N = (float)((size_t)BB * HW);
    const float mean = gsum[c] / N;
    const float var = gsum2[c] / N - mean * mean;
    const float sc = gamma[c] * rsqrtf(var + EPS_BN);
    const float sh = beta[c] - mean * sc;
#pragma unroll
    for (int i = 0; i < 32; i += 8) {
        float v = __half2float(ip[(size_t)(n0 + threadIdx.y + i) * CIN + c]);
        t[threadIdx.y + i][threadIdx.x] = fmaxf(fmaf(sc, v, sh), 0.f);
    }
    __syncthreads();
#pragma unroll
    for (int i = 0; i < 32; i += 8)
        op[(size_t)(c0 + threadIdx.y + i) * HW + n0 + threadIdx.x] = t[threadIdx.x][threadIdx.y + i];
}

// ---------------- host-side tensor map helper ----------------
typedef CUresult (*EncFn)(CUtensorMap*, CUtensorMapDataType, cuuint32_t, void*,
                          const cuuint64_t*, const cuuint64_t*, const cuuint32_t*, const cuuint32_t*,
                          CUtensorMapInterleave, CUtensorMapSwizzle, CUtensorMapL2promotion,
                          CUtensorMapFloatOOBfill);

static void make_map(EncFn enc, CUtensorMap* m, void* base, uint64_t kd, uint64_t rows, uint32_t box_rows)
{
    cuuint64_t dims[2] = { kd, rows };
    cuuint64_t strides[1] = { kd * 2 };
    cuuint32_t box[2] = { 32, box_rows };
    cuuint32_t es[2] = { 1, 1 };
    enc(m, CU_TENSOR_MAP_DATA_TYPE_FLOAT16, 2, base, dims, strides, box, es,
        CU_TENSOR_MAP_INTERLEAVE_NONE, CU_TENSOR_MAP_SWIZZLE_64B,
        CU_TENSOR_MAP_L2_PROMOTION_L2_128B, CU_TENSOR_MAP_FLOAT_OOB_FILL_NONE);
}

// ---------------- launch ----------------
extern "C" void kernel_launch(void* const* d_in, const int* in_sizes, int n_in,
                              void* d_out, int out_size)
{
    const float* x       = (const float*)d_in[0];
    const float* centers = (const float*)d_in[1];
    const float* conv1_w = (const float*)d_in[2];
    const float* conv1_b = (const float*)d_in[3];
    const float* conv2_w = (const float*)d_in[4];
    const float* bn2_g   = (const float*)d_in[5];
    const float* bn2_b   = (const float*)d_in[6];
    const float* conv3_w = (const float*)d_in[7];
    const float* conv3_b = (const float*)d_in[8];
    const float* bn3_g   = (const float*)d_in[9];
    const float* bn3_b   = (const float*)d_in[10];
    float* out = (float*)d_out;

    f16 *xT, *b1, *b2, *att16, *ct, *cs, *w1, *w2, *w3;
    float *att, *colsum, *sumA, *sum2A, *sumB, *sum2B;
    cudaGetSymbolAddress((void**)&xT, g_xT);
    cudaGetSymbolAddress((void**)&b1, g_b1);
    cudaGetSymbolAddress((void**)&b2, g_b2);
    cudaGetSymbolAddress((void**)&att16, g_att16);
    cudaGetSymbolAddress((void**)&ct, g_ct);
    cudaGetSymbolAddress((void**)&cs, g_cs);
    cudaGetSymbolAddress((void**)&w1, g_w1);
    cudaGetSymbolAddress((void**)&w2, g_w2);
    cudaGetSymbolAddress((void**)&w3, g_w3);
    cudaGetSymbolAddress((void**)&att, g_att);
    cudaGetSymbolAddress((void**)&colsum, g_colsum);
    cudaGetSymbolAddress((void**)&sumA, g_sumA);
    cudaGetSymbolAddress((void**)&sum2A, g_sum2A);
    cudaGetSymbolAddress((void**)&sumB, g_sumB);
    cudaGetSymbolAddress((void**)&sum2B, g_sum2B);

    void* pfn = nullptr;
    cudaDriverEntryPointQueryResult qr;
    cudaGetDriverEntryPoint("cuTensorMapEncodeTiled", &pfn, cudaEnableDefault, &qr);
    EncFn enc = (EncFn)pfn;

    const uint64_t RA = (uint64_t)BB * HW;
    CUtensorMap tX, tB1, tB2, tAtt, tW1, tW2, tW3, tCt, tCs;
    make_map(enc, &tX,   xT,   CIN, RA, 128);
    make_map(enc, &tB1,  b1,   COUT, RA, 128);
    make_map(enc, &tB2,  b2,   COUT, RA, 128);
    make_map(enc, &tAtt, att16, MCB, RA, 128);
    make_map(enc, &tW1,  w1,   CIN, COUT, 128);
    make_map(enc, &tW2,  w2,   COUT, CIN, 128);
    make_map(enc, &tW3,  w3,   CIN, CIN, 128);
    make_map(enc, &tCt,  ct,   COUT, MCB, 96);
    make_map(enc, &tCs,  cs,   MCB, (uint64_t)BB * COUT, 128);

    const size_t S  = (size_t)HW * CIN;
    const size_t SA = (size_t)HW * MCB;

    const int SM128 = 3 * 32768;   // 98304
    const int SM96  = 3 * 28672;   // 86016
    cudaFuncSetAttribute(gemm_tma<128, true,  true,  false>, cudaFuncAttributeMaxDynamicSharedMemorySize, SM128);
    cudaFuncSetAttribute(gemm_tma<96,  false, false, false>, cudaFuncAttributeMaxDynamicSharedMemorySize, SM96);
    cudaFuncSetAttribute(gemm_tma<128, false, true,  false>, cudaFuncAttributeMaxDynamicSharedMemorySize, SM128);
    cudaFuncSetAttribute(gemm_tma<128, false, true,  true >, cudaFuncAttributeMaxDynamicSharedMemorySize, SM128);
    cudaFuncSetAttribute(gemm_tma<128, true,  true,  true >, cudaFuncAttributeMaxDynamicSharedMemorySize, SM128);

    // 0. prep
    zero_all_kernel<<<3, 1024>>>(colsum, sumA, sum2A, sumB, sum2B);
    transpose_in_f16<<<dim3(HW / 32, CIN / 32, BB), dim3(32, 8)>>>(x, xT);
    prep_cvt_kernel<<<(3 * COUT * CIN + COUT * MCB + 255) / 256, 256>>>(
        conv1_w, conv2_w, conv3_w, centers, w1, w2, w3, ct);

    // 1. conv1 -> fp16 b1
    gemm_tma<128, true, true, false><<<dim3(4, 32, BB), 256, SM128>>>(
        tX, tW1, conv1_b, nullptr, b1, nullptr, nullptr, CIN, COUT, 0, S);

    // 2. att raw -> fp32 att
    gemm_tma<96, false, false, false><<<dim3(2, 32, BB), 256, SM96>>>(
        tB1, tCt, nullptr, att, nullptr, nullptr, nullptr, COUT, MCB, 0, SA);

    // 3. softmax (single pass, fp16 out) + batch-scaled centers
    softmax_colsum_f16<<<dim3(HW / 256, BB), 256>>>(att, colsum, att16);
    scale_centers_f16<<<dim3((COUT * MCB + 255) / 256, BB), 256>>>(centers, colsum, cs);

    // 4. recon = att_sm @ (scaled centers)^T -> fp16 b2
    gemm_tma<128, false, true, false><<<dim3(4, 32, BB), 256, SM128>>>(
        tAtt, tCs, nullptr, nullptr, b2, nullptr, nullptr, MCB, COUT, COUT, S);

    // 5. conv2 -> fp16 b1 (+fused BN stats -> sumA)
    gemm_tma<128, false, true, true><<<dim3(4, 32, BB), 256, SM128>>>(
        tB2, tW2, nullptr, nullptr, b1, sumA, sum2A, COUT, CIN, 0, S);

    // 6. BN2 apply (inline finalize) + ReLU + residual -> fp16 b2
    bn_apply_res_f16<<<(unsigned)(((size_t)BB * S / 4) / 256), 256>>>(
        b1, xT, sumA, sum2A, bn2_g, bn2_b, b2);

    // 7. conv3 -> fp16 b1 (+fused BN stats -> sumB)
    gemm_tma<128, true, true, true><<<dim3(4, 32, BB), 256, SM128>>>(
        tB2, tW3, conv3_b, nullptr, b1, sumB, sum2B, CIN, CIN, 0, S);

    // 8. BN3 apply (inline finalize) + ReLU + transpose -> out
    bn_apply_transpose_kernel<<<dim3(HW / 32, CIN / 32, BB), dim3(32, 8)>>>(
        b1, sumB, sum2B, bn3_g, bn3_b, out);
}